// round 4
// baseline (speedup 1.0000x reference)
#include <cuda_runtime.h>
#include <cuda_bf16.h>
#include <math.h>

// ---------------- problem constants ----------------
#define NN    20000     // nodes
#define EE    5000      // hyperedges
#define NNZV  200000    // incidences
#define DH    6         // sheaf dim d
#define HID   9         // MLP hidden
#define FIN   256       // input features
#define OUTD  4968      // output dim
#define PROJ  54        // DH*HID
#define ROW12 12        // padded row stride (floats) for 9-wide rows
#define NLAY  2

// ---------------- scratch (static device globals; no runtime alloc) ----------------
__device__ __align__(16) float g_xproj[NN * PROJ];      // doubles as x_state (N*d, 9) packed
__device__ __align__(16) float g_xm[NN * ROW12];        // node means, stride 12
__device__ __align__(16) float g_em[EE * ROW12];        // edge means, stride 12
__device__ __align__(16) float g_hsheaf[(size_t)NNZV * DH];
__device__ int   g_cnt_node[NN];
__device__ int   g_cnt_edge[EE];
__device__ __align__(16) float g_h0[(size_t)NN * DH * ROW12];   // (N*d, 12)
__device__ __align__(16) float g_m[(size_t)EE * DH * ROW12];    // (E*d, 12)
__device__ __align__(16) float g_acc[(size_t)NN * DH * ROW12];  // (N*d, 12)

// ---------------- zero kernels ----------------
__global__ void zero_counts_kernel() {
    int i = blockIdx.x * blockDim.x + threadIdx.x;
    if (i < NN) g_cnt_node[i] = 0;
    if (i < EE) g_cnt_edge[i] = 0;
}

__global__ void zero_layer_kernel() {
    int i = blockIdx.x * blockDim.x + threadIdx.x;
    if (i < NN * DH * ROW12) g_acc[i] = 0.f;
    if (i < EE * DH * ROW12) g_m[i] = 0.f;
}

// ---------------- input projection + per-row mean over d ----------------
// 8 rows per block, 64 threads. rows [0,NN) -> x, rows [NN,NN+EE) -> hyperedge_attr
__global__ void proj_kernel(const float* __restrict__ x,
                            const float* __restrict__ ha,
                            const float* __restrict__ W,   // (256,54) row-major
                            const float* __restrict__ b)   // (54,)
{
    __shared__ float sx[8][FIN];
    __shared__ float sout[8][PROJ];
    int r0 = blockIdx.x * 8;
    int t  = threadIdx.x;

    #pragma unroll
    for (int rr = 0; rr < 8; rr++) {
        int r = r0 + rr;
        if (r >= NN + EE) break;
        const float* src = (r < NN) ? (x + (size_t)r * FIN)
                                    : (ha + (size_t)(r - NN) * FIN);
        for (int c = t; c < FIN; c += 64) sx[rr][c] = src[c];
    }
    __syncthreads();

    if (t < PROJ) {
        float acc[8];
        float bt = b[t];
        #pragma unroll
        for (int rr = 0; rr < 8; rr++) acc[rr] = bt;
        #pragma unroll 4
        for (int c = 0; c < FIN; c++) {
            float w = W[c * PROJ + t];
            #pragma unroll
            for (int rr = 0; rr < 8; rr++) acc[rr] += w * sx[rr][c];
        }
        #pragma unroll
        for (int rr = 0; rr < 8; rr++) {
            int r = r0 + rr;
            if (r >= NN + EE) break;
            if (r < NN) g_xproj[(size_t)r * PROJ + t] = acc[rr];
            sout[rr][t] = acc[rr];
        }
    }
    __syncthreads();

    if (t < HID) {
        #pragma unroll
        for (int rr = 0; rr < 8; rr++) {
            int r = r0 + rr;
            if (r >= NN + EE) break;
            float s = 0.f;
            #pragma unroll
            for (int j = 0; j < DH; j++) s += sout[rr][j * HID + t];
            s *= (1.0f / DH);
            if (r < NN) g_xm[(size_t)r * ROW12 + t] = s;
            else        g_em[(size_t)(r - NN) * ROW12 + t] = s;
        }
    }
}

// ---------------- sheaf builder: LN(18) -> Linear(18->6) -> sigmoid; also degree counts ---------
__global__ void sheaf_kernel(const int* __restrict__ ni, const int* __restrict__ ei,
                             const float* __restrict__ lng, const float* __restrict__ lnb,
                             const float* __restrict__ sw,  const float* __restrict__ sb)
{
    __shared__ float s_sw[2 * HID * DH];  // 108
    __shared__ float s_sb[DH];
    __shared__ float s_g[2 * HID], s_b[2 * HID];
    int t = threadIdx.x;
    if (t < 2 * HID * DH) s_sw[t] = sw[t];
    if (t < DH) s_sb[t] = sb[t];
    if (t < 2 * HID) { s_g[t] = lng[t]; s_b[t] = lnb[t]; }
    __syncthreads();

    int k = blockIdx.x * blockDim.x + threadIdx.x;
    if (k >= NNZV) return;
    int n = ni[k], e = ei[k];

    float v[2 * HID];
    {
        const float4 a0 = *(const float4*)(g_xm + (size_t)n * ROW12);
        const float4 a1 = *(const float4*)(g_xm + (size_t)n * ROW12 + 4);
        v[0]=a0.x; v[1]=a0.y; v[2]=a0.z; v[3]=a0.w;
        v[4]=a1.x; v[5]=a1.y; v[6]=a1.z; v[7]=a1.w;
        v[8] = g_xm[(size_t)n * ROW12 + 8];
        const float4 b0 = *(const float4*)(g_em + (size_t)e * ROW12);
        const float4 b1 = *(const float4*)(g_em + (size_t)e * ROW12 + 4);
        v[9]=b0.x; v[10]=b0.y; v[11]=b0.z; v[12]=b0.w;
        v[13]=b1.x; v[14]=b1.y; v[15]=b1.z; v[16]=b1.w;
        v[17] = g_em[(size_t)e * ROW12 + 8];
    }
    float mean = 0.f;
    #pragma unroll
    for (int i = 0; i < 18; i++) mean += v[i];
    mean *= (1.0f / 18.0f);
    float var = 0.f;
    #pragma unroll
    for (int i = 0; i < 18; i++) { float d = v[i] - mean; var += d * d; }
    var *= (1.0f / 18.0f);
    float rs = rsqrtf(var + 1e-5f);
    float y[18];
    #pragma unroll
    for (int i = 0; i < 18; i++) y[i] = (v[i] - mean) * rs * s_g[i] + s_b[i];

    #pragma unroll
    for (int j = 0; j < DH; j++) {
        float z = s_sb[j];
        #pragma unroll
        for (int i = 0; i < 18; i++) z += y[i] * s_sw[i * DH + j];
        float h = 1.0f / (1.0f + expf(-z));
        g_hsheaf[(size_t)k * DH + j] = h;
    }
    atomicAdd(&g_cnt_node[n], 1);
    atomicAdd(&g_cnt_edge[e], 1);
}

// ---------------- per-layer: h0 = LN(x) @ conv_w[l] + conv_b[l] ----------------
__global__ void h0_kernel(const float* __restrict__ lng, const float* __restrict__ lnb,
                          const float* __restrict__ W,   const float* __restrict__ cb,
                          int l)
{
    __shared__ float sW[HID * HID];
    __shared__ float sg[HID], sb2[HID], scb[HID];
    int t = threadIdx.x;
    if (t < HID * HID) sW[t] = W[l * HID * HID + t];
    if (t < HID) { sg[t] = lng[l * HID + t]; sb2[t] = lnb[l * HID + t]; scb[t] = cb[l * HID + t]; }
    __syncthreads();

    int r = blockIdx.x * blockDim.x + threadIdx.x;
    if (r >= NN * DH) return;

    float v[HID];
    #pragma unroll
    for (int h = 0; h < HID; h++) v[h] = g_xproj[(size_t)r * HID + h];
    float mean = 0.f;
    #pragma unroll
    for (int h = 0; h < HID; h++) mean += v[h];
    mean *= (1.0f / HID);
    float var = 0.f;
    #pragma unroll
    for (int h = 0; h < HID; h++) { float d = v[h] - mean; var += d * d; }
    var *= (1.0f / HID);
    float rs = rsqrtf(var + 1e-5f);
    float y[HID];
    #pragma unroll
    for (int h = 0; h < HID; h++) y[h] = (v[h] - mean) * rs * sg[h] + sb2[h];

    #pragma unroll
    for (int c = 0; c < HID; c++) {
        float acc = scb[c];
        #pragma unroll
        for (int h = 0; h < HID; h++) acc += y[h] * sW[h * HID + c];
        g_h0[(size_t)r * ROW12 + c] = acc;
    }
}

// ---------------- scatter node->edge:  m[e*d+j] += alpha(k,j) * h0[n*d+j] ----------------
__global__ void scatter_edge_kernel(const int* __restrict__ ni, const int* __restrict__ ei)
{
    int k = blockIdx.x * blockDim.x + threadIdx.x;
    if (k >= NNZV) return;
    int n = ni[k], e = ei[k];
    const float* src = g_h0 + (size_t)n * DH * ROW12;
    float*       dst = g_m  + (size_t)e * DH * ROW12;
    const float* hs  = g_hsheaf + (size_t)k * DH;
    #pragma unroll
    for (int j = 0; j < DH; j++) {
        float al = hs[j];
        const float4 s0 = *(const float4*)(src + j * ROW12);
        const float4 s1 = *(const float4*)(src + j * ROW12 + 4);
        float s2 = src[j * ROW12 + 8];
        atomicAdd((float4*)(dst + j * ROW12),
                  make_float4(al * s0.x, al * s0.y, al * s0.z, al * s0.w));
        atomicAdd((float4*)(dst + j * ROW12 + 4),
                  make_float4(al * s1.x, al * s1.y, al * s1.z, al * s1.w));
        atomicAdd(dst + j * ROW12 + 8, al * s2);
    }
}

// ---------------- scatter edge->node: acc[n*d+j] += alpha(k,j) * Be(e) * m[e*d+j] ----------------
__global__ void scatter_node_kernel(const int* __restrict__ ni, const int* __restrict__ ei)
{
    int k = blockIdx.x * blockDim.x + threadIdx.x;
    if (k >= NNZV) return;
    int n = ni[k], e = ei[k];
    int ce = g_cnt_edge[e];
    float be = (ce > 0) ? (1.0f / (float)ce) : 0.f;
    const float* src = g_m   + (size_t)e * DH * ROW12;
    float*       dst = g_acc + (size_t)n * DH * ROW12;
    const float* hs  = g_hsheaf + (size_t)k * DH;
    #pragma unroll
    for (int j = 0; j < DH; j++) {
        float al = hs[j] * be;
        const float4 s0 = *(const float4*)(src + j * ROW12);
        const float4 s1 = *(const float4*)(src + j * ROW12 + 4);
        float s2 = src[j * ROW12 + 8];
        atomicAdd((float4*)(dst + j * ROW12),
                  make_float4(al * s0.x, al * s0.y, al * s0.z, al * s0.w));
        atomicAdd((float4*)(dst + j * ROW12 + 4),
                  make_float4(al * s1.x, al * s1.y, al * s1.z, al * s1.w));
        atomicAdd(dst + j * ROW12 + 8, al * s2);
    }
}

// ---------------- finalize: x = [elu](acc*Dv + h0 + conv_bias[l]) ----------------
__global__ void finalize_kernel(const float* __restrict__ cbias, int l)
{
    __shared__ float sb[HID];
    if (threadIdx.x < HID) sb[threadIdx.x] = cbias[l * HID + threadIdx.x];
    __syncthreads();

    int r = blockIdx.x * blockDim.x + threadIdx.x;
    if (r >= NN * DH) return;
    int n = r / DH;
    int cn = g_cnt_node[n];
    float dv = (cn > 0) ? (1.0f / (float)cn) : 0.f;
    #pragma unroll
    for (int h = 0; h < HID; h++) {
        float v = g_acc[(size_t)r * ROW12 + h] * dv
                + g_h0[(size_t)r * ROW12 + h] + sb[h];
        if (l == 0) v = (v > 0.f) ? v : expm1f(v);   // ELU on all but last layer
        g_xproj[(size_t)r * HID + h] = v;
    }
}

// ---------------- final GEMM: C[20000,4968] = Xf[20000,54] @ W2[54,4968] + b2 ----------------
// Packed f32x2 (FFMA2) GEMM: 128(M) x 256(N) tile, 8x16 microtile per thread,
// K split into 2 smem phases of 27. Thread tx owns N columns {q*64 + tx*4},
// so every Bs LDS.128 is lane-contiguous (conflict-free); As reads are
// 16-lane broadcasts.
#define GBM 128
#define GBN2 256
#define GBK 27
#define AST 132   // padded A smem stride

__global__ void __launch_bounds__(256, 1)
lin2_gemm_kernel(const float* __restrict__ Bw, const float* __restrict__ bias,
                 float* __restrict__ C)
{
    __shared__ float As[GBK * AST];    // As[k][m]   : 14.3 KB
    __shared__ float Bs[GBK * GBN2];   // Bs[k][n]   : 27.6 KB

    int n0 = blockIdx.x * GBN2;
    int m0 = blockIdx.y * GBM;
    int tid = threadIdx.x;
    int tx = tid & 15, ty = tid >> 4;

    // acc2[i][p]: M-row i (of 8), N-pair p (of 8). Pair p covers columns
    // q*64 + tx*4 + {2j, 2j+1} with q = p>>1, j = p&1.
    unsigned long long acc2[8][8];
    #pragma unroll
    for (int i = 0; i < 8; i++)
        #pragma unroll
        for (int p = 0; p < 8; p++) acc2[i][p] = 0ull;

    for (int kk = 0; kk < PROJ; kk += GBK) {
        // ---- fill As (A^T): coalesced-ish 27-float row runs from g_xproj
        for (int i = tid; i < GBM * GBK; i += 256) {
            int m = i / GBK, k = i - m * GBK;
            int gm = m0 + m;
            As[k * AST + m] = (gm < NN) ? g_xproj[(size_t)gm * PROJ + kk + k] : 0.f;
        }
        // ---- fill Bs: fully coalesced global reads
        for (int i = tid; i < GBK * GBN2; i += 256) {
            int k = i >> 8, n = i & 255;
            int gn = n0 + n;
            Bs[i] = (gn < OUTD) ? Bw[(size_t)(kk + k) * OUTD + gn] : 0.f;
        }
        __syncthreads();

        #pragma unroll 3
        for (int k = 0; k < GBK; k++) {
            // a: 8 M-values (broadcast across the 16 tx lanes)
            float a[8];
            *(float4*)&a[0] = *(const float4*)&As[k * AST + ty * 8];
            *(float4*)&a[4] = *(const float4*)&As[k * AST + ty * 8 + 4];
            unsigned long long a2[8];
            #pragma unroll
            for (int i = 0; i < 8; i++)
                asm("mov.b64 %0, {%1, %1};" : "=l"(a2[i]) : "r"(__float_as_uint(a[i])));

            // b: 16 N-values as 8 packed pairs, 4 conflict-free LDS.128
            unsigned long long b2[8];
            #pragma unroll
            for (int q = 0; q < 4; q++) {
                ulonglong2 bv = *(const ulonglong2*)&Bs[k * GBN2 + q * 64 + tx * 4];
                b2[q * 2]     = bv.x;
                b2[q * 2 + 1] = bv.y;
            }

            #pragma unroll
            for (int i = 0; i < 8; i++)
                #pragma unroll
                for (int p = 0; p < 8; p++)
                    asm("fma.rn.f32x2 %0, %1, %2, %0;"
                        : "+l"(acc2[i][p]) : "l"(a2[i]), "l"(b2[p]));
        }
        __syncthreads();
    }

    // ---- epilogue: add bias, store float4s (OUTD % 4 == 0, chunks fully in/out)
    #pragma unroll
    for (int i = 0; i < 8; i++) {
        int gm = m0 + ty * 8 + i;
        if (gm >= NN) continue;
        float* crow = C + (size_t)gm * OUTD;
        #pragma unroll
        for (int q = 0; q < 4; q++) {
            int n = n0 + q * 64 + tx * 4;
            if (n >= OUTD) continue;
            unsigned long long v0 = acc2[i][q * 2];
            unsigned long long v1 = acc2[i][q * 2 + 1];
            float4 outv;
            outv.x = __uint_as_float((unsigned)(v0))        + bias[n];
            outv.y = __uint_as_float((unsigned)(v0 >> 32))  + bias[n + 1];
            outv.z = __uint_as_float((unsigned)(v1))        + bias[n + 2];
            outv.w = __uint_as_float((unsigned)(v1 >> 32))  + bias[n + 3];
            *(float4*)(crow + n) = outv;
        }
    }
}

// ---------------- launch ----------------
extern "C" void kernel_launch(void* const* d_in, const int* in_sizes, int n_in,
                              void* d_out, int out_size)
{
    const float* x        = (const float*)d_in[0];
    const float* hedge    = (const float*)d_in[1];
    const int*   node_idx = (const int*)  d_in[2];
    const int*   edge_idx = (const int*)  d_in[3];
    const float* lin_w    = (const float*)d_in[4];
    const float* lin_b    = (const float*)d_in[5];
    const float* s_ln_g   = (const float*)d_in[6];
    const float* s_ln_b   = (const float*)d_in[7];
    const float* sheaf_w  = (const float*)d_in[8];
    const float* sheaf_b  = (const float*)d_in[9];
    const float* c_ln_g   = (const float*)d_in[10];
    const float* c_ln_b   = (const float*)d_in[11];
    const float* conv_w   = (const float*)d_in[12];
    const float* conv_b   = (const float*)d_in[13];
    const float* conv_bias= (const float*)d_in[14];
    const float* lin2_w   = (const float*)d_in[15];
    const float* lin2_b   = (const float*)d_in[16];
    float* out = (float*)d_out;

    // counts
    zero_counts_kernel<<<(NN + 255) / 256, 256>>>();
    // input projection + means
    proj_kernel<<<(NN + EE) / 8, 64>>>(x, hedge, lin_w, lin_b);
    // sheaf coefficients + degrees
    sheaf_kernel<<<(NNZV + 255) / 256, 256>>>(node_idx, edge_idx,
                                              s_ln_g, s_ln_b, sheaf_w, sheaf_b);

    for (int l = 0; l < NLAY; l++) {
        zero_layer_kernel<<<(NN * DH * ROW12 + 255) / 256, 256>>>();
        h0_kernel<<<(NN * DH + 255) / 256, 256>>>(c_ln_g, c_ln_b, conv_w, conv_b, l);
        scatter_edge_kernel<<<(NNZV + 255) / 256, 256>>>(node_idx, edge_idx);
        scatter_node_kernel<<<(NNZV + 255) / 256, 256>>>(node_idx, edge_idx);
        finalize_kernel<<<(NN * DH + 255) / 256, 256>>>(conv_bias, l);
    }

    dim3 grid((OUTD + GBN2 - 1) / GBN2, (NN + GBM - 1) / GBM);  // 20 x 157
    lin2_gemm_kernel<<<grid, 256>>>(lin2_w, lin2_b, out);
}

// round 6
// speedup vs baseline: 1.1853x; 1.1853x over previous
#include <cuda_runtime.h>
#include <cuda_bf16.h>
#include <math.h>
#include <stdint.h>

// ---------------- problem constants ----------------
#define NN    20000     // nodes
#define EE    5000      // hyperedges
#define NNZV  200000    // incidences
#define DH    6         // sheaf dim d
#define HID   9         // MLP hidden
#define FIN   256       // input features
#define OUTD  4968      // output dim
#define PROJ  54        // DH*HID
#define ROW12 12        // padded row stride (floats) for 9-wide rows
#define NLAY  2

// split-bf16 GEMM operand layout
#define KCH     64                   // bf16 per K-chunk (54 padded to 64)
#define NCHUNK  3                    // [hi|lo|hi] x [hi|hi|lo]
#define KTOT    (NCHUNK*KCH)         // 192
#define A_ROWS_PAD 20096             // 157*128
#define B_ROWS_PAD 5120              // >= 39*128

// ---------------- scratch (static device globals; no runtime alloc) ----------------
__device__ __align__(16) float g_xproj[NN * PROJ];
__device__ __align__(16) float g_xm[NN * ROW12];
__device__ __align__(16) float g_em[EE * ROW12];
__device__ __align__(16) float g_hsheaf[(size_t)NNZV * DH];
__device__ int   g_cnt_node[NN];
__device__ int   g_cnt_edge[EE];
__device__ __align__(16) float g_h0[(size_t)NN * DH * ROW12];
__device__ __align__(16) float g_m[(size_t)EE * DH * ROW12];
__device__ __align__(16) float g_acc[(size_t)NN * DH * ROW12];
__device__ __align__(16) __nv_bfloat16 g_Abf[(size_t)A_ROWS_PAD * KTOT];  // 7.7 MB
__device__ __align__(16) __nv_bfloat16 g_Bbf[(size_t)B_ROWS_PAD * KTOT];  // 2.0 MB

// ---------------- zero kernels ----------------
__global__ void zero_counts_kernel() {
    int i = blockIdx.x * blockDim.x + threadIdx.x;
    if (i < NN) g_cnt_node[i] = 0;
    if (i < EE) g_cnt_edge[i] = 0;
}
__global__ void zero_layer_kernel() {
    int i = blockIdx.x * blockDim.x + threadIdx.x;
    if (i < NN * DH * ROW12) g_acc[i] = 0.f;
    if (i < EE * DH * ROW12) g_m[i] = 0.f;
}

// ---------------- input projection + per-row mean over d ----------------
__global__ void proj_kernel(const float* __restrict__ x,
                            const float* __restrict__ ha,
                            const float* __restrict__ W,
                            const float* __restrict__ b)
{
    __shared__ float sx[8][FIN];
    __shared__ float sout[8][PROJ];
    int r0 = blockIdx.x * 8;
    int t  = threadIdx.x;

    #pragma unroll
    for (int rr = 0; rr < 8; rr++) {
        int r = r0 + rr;
        if (r >= NN + EE) break;
        const float* src = (r < NN) ? (x + (size_t)r * FIN) : (ha + (size_t)(r - NN) * FIN);
        for (int c = t; c < FIN; c += 64) sx[rr][c] = src[c];
    }
    __syncthreads();

    if (t < PROJ) {
        float acc[8];
        float bt = b[t];
        #pragma unroll
        for (int rr = 0; rr < 8; rr++) acc[rr] = bt;
        #pragma unroll 4
        for (int c = 0; c < FIN; c++) {
            float w = W[c * PROJ + t];
            #pragma unroll
            for (int rr = 0; rr < 8; rr++) acc[rr] += w * sx[rr][c];
        }
        #pragma unroll
        for (int rr = 0; rr < 8; rr++) {
            int r = r0 + rr;
            if (r >= NN + EE) break;
            if (r < NN) g_xproj[(size_t)r * PROJ + t] = acc[rr];
            sout[rr][t] = acc[rr];
        }
    }
    __syncthreads();

    if (t < HID) {
        #pragma unroll
        for (int rr = 0; rr < 8; rr++) {
            int r = r0 + rr;
            if (r >= NN + EE) break;
            float s = 0.f;
            #pragma unroll
            for (int j = 0; j < DH; j++) s += sout[rr][j * HID + t];
            s *= (1.0f / DH);
            if (r < NN) g_xm[(size_t)r * ROW12 + t] = s;
            else        g_em[(size_t)(r - NN) * ROW12 + t] = s;
        }
    }
}

// ---------------- sheaf builder ----------------
__global__ void sheaf_kernel(const int* __restrict__ ni, const int* __restrict__ ei,
                             const float* __restrict__ lng, const float* __restrict__ lnb,
                             const float* __restrict__ sw,  const float* __restrict__ sb)
{
    __shared__ float s_sw[2 * HID * DH];
    __shared__ float s_sb[DH];
    __shared__ float s_g[2 * HID], s_b[2 * HID];
    int t = threadIdx.x;
    if (t < 2 * HID * DH) s_sw[t] = sw[t];
    if (t < DH) s_sb[t] = sb[t];
    if (t < 2 * HID) { s_g[t] = lng[t]; s_b[t] = lnb[t]; }
    __syncthreads();

    int k = blockIdx.x * blockDim.x + threadIdx.x;
    if (k >= NNZV) return;
    int n = ni[k], e = ei[k];

    float v[2 * HID];
    {
        const float4 a0 = *(const float4*)(g_xm + (size_t)n * ROW12);
        const float4 a1 = *(const float4*)(g_xm + (size_t)n * ROW12 + 4);
        v[0]=a0.x; v[1]=a0.y; v[2]=a0.z; v[3]=a0.w;
        v[4]=a1.x; v[5]=a1.y; v[6]=a1.z; v[7]=a1.w;
        v[8] = g_xm[(size_t)n * ROW12 + 8];
        const float4 b0 = *(const float4*)(g_em + (size_t)e * ROW12);
        const float4 b1 = *(const float4*)(g_em + (size_t)e * ROW12 + 4);
        v[9]=b0.x; v[10]=b0.y; v[11]=b0.z; v[12]=b0.w;
        v[13]=b1.x; v[14]=b1.y; v[15]=b1.z; v[16]=b1.w;
        v[17] = g_em[(size_t)e * ROW12 + 8];
    }
    float mean = 0.f;
    #pragma unroll
    for (int i = 0; i < 18; i++) mean += v[i];
    mean *= (1.0f / 18.0f);
    float var = 0.f;
    #pragma unroll
    for (int i = 0; i < 18; i++) { float d = v[i] - mean; var += d * d; }
    var *= (1.0f / 18.0f);
    float rs = rsqrtf(var + 1e-5f);
    float y[18];
    #pragma unroll
    for (int i = 0; i < 18; i++) y[i] = (v[i] - mean) * rs * s_g[i] + s_b[i];

    #pragma unroll
    for (int j = 0; j < DH; j++) {
        float z = s_sb[j];
        #pragma unroll
        for (int i = 0; i < 18; i++) z += y[i] * s_sw[i * DH + j];
        float h = 1.0f / (1.0f + expf(-z));
        g_hsheaf[(size_t)k * DH + j] = h;
    }
    atomicAdd(&g_cnt_node[n], 1);
    atomicAdd(&g_cnt_edge[e], 1);
}

// ---------------- per-layer: h0 = LN(x) @ conv_w[l] + conv_b[l] ----------------
__global__ void h0_kernel(const float* __restrict__ lng, const float* __restrict__ lnb,
                          const float* __restrict__ W,   const float* __restrict__ cb,
                          int l)
{
    __shared__ float sW[HID * HID];
    __shared__ float sg[HID], sb2[HID], scb[HID];
    int t = threadIdx.x;
    if (t < HID * HID) sW[t] = W[l * HID * HID + t];
    if (t < HID) { sg[t] = lng[l * HID + t]; sb2[t] = lnb[l * HID + t]; scb[t] = cb[l * HID + t]; }
    __syncthreads();

    int r = blockIdx.x * blockDim.x + threadIdx.x;
    if (r >= NN * DH) return;

    float v[HID];
    #pragma unroll
    for (int h = 0; h < HID; h++) v[h] = g_xproj[(size_t)r * HID + h];
    float mean = 0.f;
    #pragma unroll
    for (int h = 0; h < HID; h++) mean += v[h];
    mean *= (1.0f / HID);
    float var = 0.f;
    #pragma unroll
    for (int h = 0; h < HID; h++) { float d = v[h] - mean; var += d * d; }
    var *= (1.0f / HID);
    float rs = rsqrtf(var + 1e-5f);
    float y[HID];
    #pragma unroll
    for (int h = 0; h < HID; h++) y[h] = (v[h] - mean) * rs * sg[h] + sb2[h];

    #pragma unroll
    for (int c = 0; c < HID; c++) {
        float acc = scb[c];
        #pragma unroll
        for (int h = 0; h < HID; h++) acc += y[h] * sW[h * HID + c];
        g_h0[(size_t)r * ROW12 + c] = acc;
    }
}

// ---------------- scatter node->edge ----------------
__global__ void scatter_edge_kernel(const int* __restrict__ ni, const int* __restrict__ ei)
{
    int k = blockIdx.x * blockDim.x + threadIdx.x;
    if (k >= NNZV) return;
    int n = ni[k], e = ei[k];
    const float* src = g_h0 + (size_t)n * DH * ROW12;
    float*       dst = g_m  + (size_t)e * DH * ROW12;
    const float* hs  = g_hsheaf + (size_t)k * DH;
    #pragma unroll
    for (int j = 0; j < DH; j++) {
        float al = hs[j];
        const float4 s0 = *(const float4*)(src + j * ROW12);
        const float4 s1 = *(const float4*)(src + j * ROW12 + 4);
        float s2 = src[j * ROW12 + 8];
        atomicAdd((float4*)(dst + j * ROW12),
                  make_float4(al * s0.x, al * s0.y, al * s0.z, al * s0.w));
        atomicAdd((float4*)(dst + j * ROW12 + 4),
                  make_float4(al * s1.x, al * s1.y, al * s1.z, al * s1.w));
        atomicAdd(dst + j * ROW12 + 8, al * s2);
    }
}

// ---------------- scatter edge->node ----------------
__global__ void scatter_node_kernel(const int* __restrict__ ni, const int* __restrict__ ei)
{
    int k = blockIdx.x * blockDim.x + threadIdx.x;
    if (k >= NNZV) return;
    int n = ni[k], e = ei[k];
    int ce = g_cnt_edge[e];
    float be = (ce > 0) ? (1.0f / (float)ce) : 0.f;
    const float* src = g_m   + (size_t)e * DH * ROW12;
    float*       dst = g_acc + (size_t)n * DH * ROW12;
    const float* hs  = g_hsheaf + (size_t)k * DH;
    #pragma unroll
    for (int j = 0; j < DH; j++) {
        float al = hs[j] * be;
        const float4 s0 = *(const float4*)(src + j * ROW12);
        const float4 s1 = *(const float4*)(src + j * ROW12 + 4);
        float s2 = src[j * ROW12 + 8];
        atomicAdd((float4*)(dst + j * ROW12),
                  make_float4(al * s0.x, al * s0.y, al * s0.z, al * s0.w));
        atomicAdd((float4*)(dst + j * ROW12 + 4),
                  make_float4(al * s1.x, al * s1.y, al * s1.z, al * s1.w));
        atomicAdd(dst + j * ROW12 + 8, al * s2);
    }
}

// ---------------- finalize ----------------
__global__ void finalize_kernel(const float* __restrict__ cbias, int l)
{
    __shared__ float sb[HID];
    if (threadIdx.x < HID) sb[threadIdx.x] = cbias[l * HID + threadIdx.x];
    __syncthreads();

    int r = blockIdx.x * blockDim.x + threadIdx.x;
    if (r >= NN * DH) return;
    int n = r / DH;
    int cn = g_cnt_node[n];
    float dv = (cn > 0) ? (1.0f / (float)cn) : 0.f;
    #pragma unroll
    for (int h = 0; h < HID; h++) {
        float v = g_acc[(size_t)r * ROW12 + h] * dv
                + g_h0[(size_t)r * ROW12 + h] + sb[h];
        if (l == 0) v = (v > 0.f) ? v : expm1f(v);
        g_xproj[(size_t)r * HID + h] = v;
    }
}

// ---------------- GEMM prep: fp32 -> split bf16 operands ----------------
// A' rows [A_hi | A_lo | A_hi], K padded 54->64 per chunk, rows padded to 20096
__global__ void prep_A_kernel()
{
    int idx = blockIdx.x * blockDim.x + threadIdx.x;
    if (idx >= A_ROWS_PAD * KTOT) return;
    int r = idx / KTOT, k = idx - r * KTOT;
    int region = k >> 6, j = k & 63;
    __nv_bfloat16 o = __float2bfloat16(0.f);
    if (r < NN && j < PROJ) {
        float a = g_xproj[(size_t)r * PROJ + j];
        __nv_bfloat16 h = __float2bfloat16(a);
        if (region == 1) o = __float2bfloat16(a - __bfloat162float(h));
        else             o = h;
    }
    g_Abf[idx] = o;
}

// B' rows [B_hi | B_hi | B_lo], B[n][k] = W2[k][n], rows padded to 5120
__global__ void prep_B_kernel(const float* __restrict__ W2)
{
    int idx = blockIdx.x * blockDim.x + threadIdx.x;
    if (idx >= B_ROWS_PAD * KTOT) return;
    int n = idx / KTOT, k = idx - n * KTOT;
    int region = k >> 6, j = k & 63;
    __nv_bfloat16 o = __float2bfloat16(0.f);
    if (n < OUTD && j < PROJ) {
        float a = W2[(size_t)j * OUTD + n];
        __nv_bfloat16 h = __float2bfloat16(a);
        if (region == 2) o = __float2bfloat16(a - __bfloat162float(h));
        else             o = h;
    }
    g_Bbf[idx] = o;
}

// ---------------- HMMA lin2 GEMM ----------------
// C[20000,4968] = A'[M,192] . B'[N,192]^T + bias, mma.sync m16n8k16 bf16, f32 accum.
// CTA tile 128x128, 8 warps (2x4), warp tile 64x32 (4x4 mma tiles).
// 3 K-chunks of 64 bf16 through static smem (stride 72: rows 4 banks apart).
#define LDSM_X4(r, addr) \
    asm volatile("ldmatrix.sync.aligned.m8n8.x4.shared.b16 {%0,%1,%2,%3}, [%4];" \
        : "=r"((r)[0]), "=r"((r)[1]), "=r"((r)[2]), "=r"((r)[3]) : "r"(addr))
#define MMA16816(d, a, b0, b1) \
    asm volatile("mma.sync.aligned.m16n8k16.row.col.f32.bf16.bf16.f32 " \
        "{%0,%1,%2,%3}, {%4,%5,%6,%7}, {%8,%9}, {%0,%1,%2,%3};" \
        : "+f"((d)[0]), "+f"((d)[1]), "+f"((d)[2]), "+f"((d)[3]) \
        : "r"((a)[0]), "r"((a)[1]), "r"((a)[2]), "r"((a)[3]), "r"(b0), "r"(b1))

__device__ __forceinline__ uint32_t smem_u32(const void* p) {
    uint32_t a;
    asm("{ .reg .u64 t; cvta.to.shared.u64 t, %1; cvt.u32.u64 %0, t; }" : "=r"(a) : "l"(p));
    return a;
}

#define SAST 72   // smem bf16 stride per row

__global__ void __launch_bounds__(256, 2)
lin2_mma_kernel(const float* __restrict__ bias, float* __restrict__ C)
{
    __shared__ __align__(16) __nv_bfloat16 sA[128][SAST];
    __shared__ __align__(16) __nv_bfloat16 sB[128][SAST];
    __shared__ float sbias[128];

    int tid = threadIdx.x, lane = tid & 31, wid = tid >> 5;
    int wm = wid >> 2, wn = wid & 3;            // warp grid 2(M) x 4(N)
    int n0 = blockIdx.x * 128, m0 = blockIdx.y * 128;

    for (int i = tid; i < 128; i += 256) {
        int n = n0 + i;
        sbias[i] = (n < OUTD) ? bias[n] : 0.f;
    }

    float acc[4][4][4];
    #pragma unroll
    for (int mt = 0; mt < 4; mt++)
        #pragma unroll
        for (int nt = 0; nt < 4; nt++)
            #pragma unroll
            for (int q = 0; q < 4; q++) acc[mt][nt][q] = 0.f;

    for (int ch = 0; ch < NCHUNK; ch++) {
        // load A/B chunk tiles (64 bf16 = 8 uint4 per row)
        for (int i = tid; i < 1024; i += 256) {
            int r = i >> 3, c = (i & 7) * 8;
            *(uint4*)&sA[r][c] = *(const uint4*)(g_Abf + (size_t)(m0 + r) * KTOT + ch * KCH + c);
        }
        for (int i = tid; i < 1024; i += 256) {
            int r = i >> 3, c = (i & 7) * 8;
            *(uint4*)&sB[r][c] = *(const uint4*)(g_Bbf + (size_t)(n0 + r) * KTOT + ch * KCH + c);
        }
        __syncthreads();

        #pragma unroll
        for (int ks = 0; ks < 4; ks++) {      // 4 k16 steps per chunk
            uint32_t af[4][4], bf[2][4];
            // A fragments: row = lane&15, k half = lane>>4
            #pragma unroll
            for (int mt = 0; mt < 4; mt++) {
                int row = wm * 64 + mt * 16 + (lane & 15);
                int col = ks * 16 + (lane >> 4) * 8;
                LDSM_X4(af[mt], smem_u32(&sA[row][col]));
            }
            // B fragments: x4 covers two n8 tiles
            #pragma unroll
            for (int p = 0; p < 2; p++) {
                int q = lane >> 3, rl = lane & 7;
                int nrow = wn * 32 + p * 16 + (q >> 1) * 8 + rl;
                int col = ks * 16 + (q & 1) * 8;
                LDSM_X4(bf[p], smem_u32(&sB[nrow][col]));
            }
            #pragma unroll
            for (int mt = 0; mt < 4; mt++)
                #pragma unroll
                for (int nt = 0; nt < 4; nt++)
                    MMA16816(acc[mt][nt], af[mt],
                             bf[nt >> 1][(nt & 1) * 2], bf[nt >> 1][(nt & 1) * 2 + 1]);
        }
        __syncthreads();
    }

    // epilogue: c0/c1 -> (row gid, col 2t), c2/c3 -> (row gid+8)
    int gid = lane >> 2, tig = lane & 3;
    #pragma unroll
    for (int mt = 0; mt < 4; mt++) {
        int r0 = m0 + wm * 64 + mt * 16 + gid;
        int r1 = r0 + 8;
        #pragma unroll
        for (int nt = 0; nt < 4; nt++) {
            int lc = wn * 32 + nt * 8 + tig * 2;
            int c  = n0 + lc;
            if (c < OUTD) {    // OUTD % 8 == 0: n8 tile fully in or out
                float b0 = sbias[lc], b1 = sbias[lc + 1];
                if (r0 < NN) {
                    float2 v = make_float2(acc[mt][nt][0] + b0, acc[mt][nt][1] + b1);
                    *(float2*)(C + (size_t)r0 * OUTD + c) = v;
                }
                if (r1 < NN) {
                    float2 v = make_float2(acc[mt][nt][2] + b0, acc[mt][nt][3] + b1);
                    *(float2*)(C + (size_t)r1 * OUTD + c) = v;
                }
            }
        }
    }
}

// ---------------- launch ----------------
extern "C" void kernel_launch(void* const* d_in, const int* in_sizes, int n_in,
                              void* d_out, int out_size)
{
    const float* x        = (const float*)d_in[0];
    const float* hedge    = (const float*)d_in[1];
    const int*   node_idx = (const int*)  d_in[2];
    const int*   edge_idx = (const int*)  d_in[3];
    const float* lin_w    = (const float*)d_in[4];
    const float* lin_b    = (const float*)d_in[5];
    const float* s_ln_g   = (const float*)d_in[6];
    const float* s_ln_b   = (const float*)d_in[7];
    const float* sheaf_w  = (const float*)d_in[8];
    const float* sheaf_b  = (const float*)d_in[9];
    const float* c_ln_g   = (const float*)d_in[10];
    const float* c_ln_b   = (const float*)d_in[11];
    const float* conv_w   = (const float*)d_in[12];
    const float* conv_b   = (const float*)d_in[13];
    const float* conv_bias= (const float*)d_in[14];
    const float* lin2_w   = (const float*)d_in[15];
    const float* lin2_b   = (const float*)d_in[16];
    float* out = (float*)d_out;

    zero_counts_kernel<<<(NN + 255) / 256, 256>>>();
    proj_kernel<<<(NN + EE) / 8, 64>>>(x, hedge, lin_w, lin_b);
    sheaf_kernel<<<(NNZV + 255) / 256, 256>>>(node_idx, edge_idx,
                                              s_ln_g, s_ln_b, sheaf_w, sheaf_b);
    // B operand prep is independent of the layer loop
    prep_B_kernel<<<(B_ROWS_PAD * KTOT + 255) / 256, 256>>>(lin2_w);

    for (int l = 0; l < NLAY; l++) {
        zero_layer_kernel<<<(NN * DH * ROW12 + 255) / 256, 256>>>();
        h0_kernel<<<(NN * DH + 255) / 256, 256>>>(c_ln_g, c_ln_b, conv_w, conv_b, l);
        scatter_edge_kernel<<<(NNZV + 255) / 256, 256>>>(node_idx, edge_idx);
        scatter_node_kernel<<<(NNZV + 255) / 256, 256>>>(node_idx, edge_idx);
        finalize_kernel<<<(NN * DH + 255) / 256, 256>>>(conv_bias, l);
    }

    prep_A_kernel<<<(A_ROWS_PAD * KTOT + 255) / 256, 256>>>();

    dim3 grid((OUTD + 127) / 128, (NN + 127) / 128);   // 39 x 157
    lin2_mma_kernel<<<grid, 256>>>(lin2_b, out);
}

// round 7
// speedup vs baseline: 1.2124x; 1.0229x over previous
#include <cuda_runtime.h>
#include <cuda_bf16.h>
#include <math.h>
#include <stdint.h>

// ---------------- problem constants ----------------
#define NN    20000     // nodes
#define EE    5000      // hyperedges
#define NNZV  200000    // incidences
#define DH    6         // sheaf dim d
#define HID   9         // MLP hidden
#define FIN   256       // input features
#define OUTD  4968      // output dim
#define PROJ  54        // DH*HID
#define ROW12 12        // padded row stride (floats) for 9-wide rows
#define NLAY  2

// split-bf16 GEMM operand layout
#define KCH     64                   // bf16 per K-chunk (54 padded to 64)
#define NCHUNK  3                    // [hi|lo|hi] x [hi|hi|lo]
#define KTOT    (NCHUNK*KCH)         // 192
#define A_ROWS_PAD 20096             // 157*128
#define B_ROWS_PAD 5120              // >= 39*128

// ---------------- scratch (static device globals; no runtime alloc) ----------------
// NOTE: device globals are zero-initialized at module load; the padding regions
// of g_Abf/g_Bbf (cols 54..63 per chunk, rows >= NN/OUTD) are NEVER written by
// any kernel, so they stay zero across graph replays.
__device__ __align__(16) float g_xproj[NN * PROJ];
__device__ __align__(16) float g_xm[NN * ROW12];
__device__ __align__(16) float g_em[EE * ROW12];
__device__ __align__(16) float g_hsheaf[(size_t)NNZV * DH];
__device__ int   g_cnt_node[NN];
__device__ int   g_cnt_edge[EE];
__device__ int   g_noff[NN + 1];
__device__ int   g_eoff[EE + 1];
__device__ int   g_ncur[NN];
__device__ int   g_ecur[EE];
__device__ __align__(8) int2 g_elist[NNZV];   // (k, node)
__device__ __align__(8) int2 g_nlist[NNZV];   // (k, edge)
__device__ __align__(16) float g_h0[(size_t)NN * DH * ROW12];
__device__ __align__(16) float g_m[(size_t)EE * DH * ROW12];
__device__ __align__(16) __nv_bfloat16 g_Abf[(size_t)A_ROWS_PAD * KTOT];  // 7.7 MB
__device__ __align__(16) __nv_bfloat16 g_Bbf[(size_t)B_ROWS_PAD * KTOT];  // 2.0 MB

// ---------------- zero counts + cursors ----------------
__global__ void zero_counts_kernel() {
    int i = blockIdx.x * blockDim.x + threadIdx.x;
    if (i < NN) { g_cnt_node[i] = 0; g_ncur[i] = 0; }
    if (i < EE) { g_cnt_edge[i] = 0; g_ecur[i] = 0; }
}

// ---------------- input projection + per-row mean over d ----------------
__global__ void proj_kernel(const float* __restrict__ x,
                            const float* __restrict__ ha,
                            const float* __restrict__ W,
                            const float* __restrict__ b)
{
    __shared__ float sx[8][FIN];
    __shared__ float sout[8][PROJ];
    int r0 = blockIdx.x * 8;
    int t  = threadIdx.x;

    #pragma unroll
    for (int rr = 0; rr < 8; rr++) {
        int r = r0 + rr;
        if (r >= NN + EE) break;
        const float* src = (r < NN) ? (x + (size_t)r * FIN) : (ha + (size_t)(r - NN) * FIN);
        for (int c = t; c < FIN; c += 64) sx[rr][c] = src[c];
    }
    __syncthreads();

    if (t < PROJ) {
        float acc[8];
        float bt = b[t];
        #pragma unroll
        for (int rr = 0; rr < 8; rr++) acc[rr] = bt;
        #pragma unroll 4
        for (int c = 0; c < FIN; c++) {
            float w = W[c * PROJ + t];
            #pragma unroll
            for (int rr = 0; rr < 8; rr++) acc[rr] += w * sx[rr][c];
        }
        #pragma unroll
        for (int rr = 0; rr < 8; rr++) {
            int r = r0 + rr;
            if (r >= NN + EE) break;
            if (r < NN) g_xproj[(size_t)r * PROJ + t] = acc[rr];
            sout[rr][t] = acc[rr];
        }
    }
    __syncthreads();

    if (t < HID) {
        #pragma unroll
        for (int rr = 0; rr < 8; rr++) {
            int r = r0 + rr;
            if (r >= NN + EE) break;
            float s = 0.f;
            #pragma unroll
            for (int j = 0; j < DH; j++) s += sout[rr][j * HID + t];
            s *= (1.0f / DH);
            if (r < NN) g_xm[(size_t)r * ROW12 + t] = s;
            else        g_em[(size_t)(r - NN) * ROW12 + t] = s;
        }
    }
}

// ---------------- sheaf builder (alpha + degree counts) ----------------
__global__ void sheaf_kernel(const int* __restrict__ ni, const int* __restrict__ ei,
                             const float* __restrict__ lng, const float* __restrict__ lnb,
                             const float* __restrict__ sw,  const float* __restrict__ sb)
{
    __shared__ float s_sw[2 * HID * DH];
    __shared__ float s_sb[DH];
    __shared__ float s_g[2 * HID], s_b[2 * HID];
    int t = threadIdx.x;
    if (t < 2 * HID * DH) s_sw[t] = sw[t];
    if (t < DH) s_sb[t] = sb[t];
    if (t < 2 * HID) { s_g[t] = lng[t]; s_b[t] = lnb[t]; }
    __syncthreads();

    int k = blockIdx.x * blockDim.x + threadIdx.x;
    if (k >= NNZV) return;
    int n = ni[k], e = ei[k];

    float v[2 * HID];
    {
        const float4 a0 = *(const float4*)(g_xm + (size_t)n * ROW12);
        const float4 a1 = *(const float4*)(g_xm + (size_t)n * ROW12 + 4);
        v[0]=a0.x; v[1]=a0.y; v[2]=a0.z; v[3]=a0.w;
        v[4]=a1.x; v[5]=a1.y; v[6]=a1.z; v[7]=a1.w;
        v[8] = g_xm[(size_t)n * ROW12 + 8];
        const float4 b0 = *(const float4*)(g_em + (size_t)e * ROW12);
        const float4 b1 = *(const float4*)(g_em + (size_t)e * ROW12 + 4);
        v[9]=b0.x; v[10]=b0.y; v[11]=b0.z; v[12]=b0.w;
        v[13]=b1.x; v[14]=b1.y; v[15]=b1.z; v[16]=b1.w;
        v[17] = g_em[(size_t)e * ROW12 + 8];
    }
    float mean = 0.f;
    #pragma unroll
    for (int i = 0; i < 18; i++) mean += v[i];
    mean *= (1.0f / 18.0f);
    float var = 0.f;
    #pragma unroll
    for (int i = 0; i < 18; i++) { float d = v[i] - mean; var += d * d; }
    var *= (1.0f / 18.0f);
    float rs = rsqrtf(var + 1e-5f);
    float y[18];
    #pragma unroll
    for (int i = 0; i < 18; i++) y[i] = (v[i] - mean) * rs * s_g[i] + s_b[i];

    #pragma unroll
    for (int j = 0; j < DH; j++) {
        float z = s_sb[j];
        #pragma unroll
        for (int i = 0; i < 18; i++) z += y[i] * s_sw[i * DH + j];
        float h = 1.0f / (1.0f + expf(-z));
        g_hsheaf[(size_t)k * DH + j] = h;
    }
    atomicAdd(&g_cnt_node[n], 1);
    atomicAdd(&g_cnt_edge[e], 1);
}

// ---------------- single-block exclusive scans (block 0: edges, block 1: nodes) ----------------
__global__ void scan_kernel()
{
    __shared__ int s[1024];
    __shared__ int carry;
    const int* cnt;
    int* off;
    int len;
    if (blockIdx.x == 0) { cnt = g_cnt_edge; off = g_eoff; len = EE; }
    else                 { cnt = g_cnt_node; off = g_noff; len = NN; }
    int t = threadIdx.x;
    if (t == 0) carry = 0;
    __syncthreads();

    for (int base = 0; base < len; base += 1024) {
        int i = base + t;
        int v = (i < len) ? cnt[i] : 0;
        s[t] = v;
        __syncthreads();
        #pragma unroll
        for (int d = 1; d < 1024; d <<= 1) {
            int add = (t >= d) ? s[t - d] : 0;
            __syncthreads();
            s[t] += add;
            __syncthreads();
        }
        int c = carry;
        if (i < len) off[i] = c + s[t] - v;
        int total = s[1023];
        __syncthreads();
        if (t == 0) carry = c + total;
        __syncthreads();
    }
    if (t == 0) off[len] = carry;
}

// ---------------- CSR fill ----------------
__global__ void fill_kernel(const int* __restrict__ ni, const int* __restrict__ ei)
{
    int k = blockIdx.x * blockDim.x + threadIdx.x;
    if (k >= NNZV) return;
    int n = ni[k], e = ei[k];
    int pe = atomicAdd(&g_ecur[e], 1);
    g_elist[g_eoff[e] + pe] = make_int2(k, n);
    int pn = atomicAdd(&g_ncur[n], 1);
    g_nlist[g_noff[n] + pn] = make_int2(k, e);
}

// ---------------- per-layer: h0 = LN(x) @ conv_w[l] + conv_b[l] ----------------
__global__ void h0_kernel(const float* __restrict__ lng, const float* __restrict__ lnb,
                          const float* __restrict__ W,   const float* __restrict__ cb,
                          int l)
{
    __shared__ float sW[HID * HID];
    __shared__ float sg[HID], sb2[HID], scb[HID];
    int t = threadIdx.x;
    if (t < HID * HID) sW[t] = W[l * HID * HID + t];
    if (t < HID) { sg[t] = lng[l * HID + t]; sb2[t] = lnb[l * HID + t]; scb[t] = cb[l * HID + t]; }
    __syncthreads();

    int r = blockIdx.x * blockDim.x + threadIdx.x;
    if (r >= NN * DH) return;

    float v[HID];
    #pragma unroll
    for (int h = 0; h < HID; h++) v[h] = g_xproj[(size_t)r * HID + h];
    float mean = 0.f;
    #pragma unroll
    for (int h = 0; h < HID; h++) mean += v[h];
    mean *= (1.0f / HID);
    float var = 0.f;
    #pragma unroll
    for (int h = 0; h < HID; h++) { float d = v[h] - mean; var += d * d; }
    var *= (1.0f / HID);
    float rs = rsqrtf(var + 1e-5f);
    float y[HID];
    #pragma unroll
    for (int h = 0; h < HID; h++) y[h] = (v[h] - mean) * rs * sg[h] + sb2[h];

    #pragma unroll
    for (int c = 0; c < HID; c++) {
        float acc = scb[c];
        #pragma unroll
        for (int h = 0; h < HID; h++) acc += y[h] * sW[h * HID + c];
        g_h0[(size_t)r * ROW12 + c] = acc;
    }
}

// ---------------- edge gather: m[e*d+j] = Be * sum_k alpha(k,j) h0[n*d+j] ----------------
__global__ void edge_gather_kernel()
{
    int idx = blockIdx.x * blockDim.x + threadIdx.x;
    if (idx >= EE * DH) return;
    int e = idx / DH, j = idx - e * DH;
    int s = g_eoff[e], t = g_eoff[e + 1];
    float be = (t > s) ? (1.0f / (float)(t - s)) : 0.f;

    float a0 = 0.f, a1 = 0.f, a2 = 0.f, a3 = 0.f, a4 = 0.f,
          a5 = 0.f, a6 = 0.f, a7 = 0.f, a8 = 0.f;
    for (int p = s; p < t; p++) {
        int2 kn = g_elist[p];
        float al = g_hsheaf[(size_t)kn.x * DH + j];
        const float* src = g_h0 + ((size_t)kn.y * DH + j) * ROW12;
        float4 v0 = *(const float4*)src;
        float4 v1 = *(const float4*)(src + 4);
        float  v2 = src[8];
        a0 += al * v0.x; a1 += al * v0.y; a2 += al * v0.z; a3 += al * v0.w;
        a4 += al * v1.x; a5 += al * v1.y; a6 += al * v1.z; a7 += al * v1.w;
        a8 += al * v2;
    }
    float* dst = g_m + (size_t)idx * ROW12;
    *(float4*)dst       = make_float4(a0 * be, a1 * be, a2 * be, a3 * be);
    *(float4*)(dst + 4) = make_float4(a4 * be, a5 * be, a6 * be, a7 * be);
    dst[8] = a8 * be;
}

// ---------------- node gather + finalize (+ bf16 A-operand emit on last layer) ------------
__global__ void node_gather_fin_kernel(const float* __restrict__ cbias, int l)
{
    __shared__ float sb[HID];
    if (threadIdx.x < HID) sb[threadIdx.x] = cbias[l * HID + threadIdx.x];
    __syncthreads();

    int idx = blockIdx.x * blockDim.x + threadIdx.x;
    if (idx >= NN * DH) return;
    int n = idx / DH, j = idx - n * DH;
    int s = g_noff[n], t = g_noff[n + 1];
    float dv = (t > s) ? (1.0f / (float)(t - s)) : 0.f;

    float a0 = 0.f, a1 = 0.f, a2 = 0.f, a3 = 0.f, a4 = 0.f,
          a5 = 0.f, a6 = 0.f, a7 = 0.f, a8 = 0.f;
    for (int p = s; p < t; p++) {
        int2 ke = g_nlist[p];
        float al = g_hsheaf[(size_t)ke.x * DH + j];
        const float* src = g_m + ((size_t)ke.y * DH + j) * ROW12;
        float4 v0 = *(const float4*)src;
        float4 v1 = *(const float4*)(src + 4);
        float  v2 = src[8];
        a0 += al * v0.x; a1 += al * v0.y; a2 += al * v0.z; a3 += al * v0.w;
        a4 += al * v1.x; a5 += al * v1.y; a6 += al * v1.z; a7 += al * v1.w;
        a8 += al * v2;
    }

    const float* h0r = g_h0 + (size_t)idx * ROW12;
    float o[HID];
    o[0] = a0 * dv + h0r[0] + sb[0];
    o[1] = a1 * dv + h0r[1] + sb[1];
    o[2] = a2 * dv + h0r[2] + sb[2];
    o[3] = a3 * dv + h0r[3] + sb[3];
    o[4] = a4 * dv + h0r[4] + sb[4];
    o[5] = a5 * dv + h0r[5] + sb[5];
    o[6] = a6 * dv + h0r[6] + sb[6];
    o[7] = a7 * dv + h0r[7] + sb[7];
    o[8] = a8 * dv + h0r[8] + sb[8];

    if (l == 0) {
        #pragma unroll
        for (int h = 0; h < HID; h++) {
            float v = o[h];
            v = (v > 0.f) ? v : expm1f(v);   // ELU
            g_xproj[(size_t)idx * HID + h] = v;
        }
    } else {
        // final layer: emit split-bf16 A' row directly  [hi | lo | hi]
        __nv_bfloat16* arow = g_Abf + (size_t)n * KTOT + j * HID;
        #pragma unroll
        for (int h = 0; h < HID; h++) {
            float v = o[h];
            __nv_bfloat16 hi = __float2bfloat16(v);
            __nv_bfloat16 lo = __float2bfloat16(v - __bfloat162float(hi));
            arow[h]            = hi;
            arow[KCH + h]      = lo;
            arow[2 * KCH + h]  = hi;
        }
    }
}

// ---------------- B' prep: [B_hi | B_hi | B_lo], B[n][k] = W2[k][n] ----------------
__global__ void prep_B_kernel(const float* __restrict__ W2)
{
    int idx = blockIdx.x * blockDim.x + threadIdx.x;
    if (idx >= B_ROWS_PAD * KTOT) return;
    int n = idx / KTOT, k = idx - n * KTOT;
    int region = k >> 6, j = k & 63;
    __nv_bfloat16 o = __float2bfloat16(0.f);
    if (n < OUTD && j < PROJ) {
        float a = W2[(size_t)j * OUTD + n];
        __nv_bfloat16 h = __float2bfloat16(a);
        if (region == 2) o = __float2bfloat16(a - __bfloat162float(h));
        else             o = h;
    }
    g_Bbf[idx] = o;
}

// ---------------- HMMA lin2 GEMM (unchanged from R5 passing version) ----------------
#define LDSM_X4(r, addr) \
    asm volatile("ldmatrix.sync.aligned.m8n8.x4.shared.b16 {%0,%1,%2,%3}, [%4];" \
        : "=r"((r)[0]), "=r"((r)[1]), "=r"((r)[2]), "=r"((r)[3]) : "r"(addr))
#define MMA16816(d, a, b0, b1) \
    asm volatile("mma.sync.aligned.m16n8k16.row.col.f32.bf16.bf16.f32 " \
        "{%0,%1,%2,%3}, {%4,%5,%6,%7}, {%8,%9}, {%0,%1,%2,%3};" \
        : "+f"((d)[0]), "+f"((d)[1]), "+f"((d)[2]), "+f"((d)[3]) \
        : "r"((a)[0]), "r"((a)[1]), "r"((a)[2]), "r"((a)[3]), "r"(b0), "r"(b1))

__device__ __forceinline__ uint32_t smem_u32(const void* p) {
    uint32_t a;
    asm("{ .reg .u64 t; cvta.to.shared.u64 t, %1; cvt.u32.u64 %0, t; }" : "=r"(a) : "l"(p));
    return a;
}

#define SAST 72   // smem bf16 stride per row

__global__ void __launch_bounds__(256, 2)
lin2_mma_kernel(const float* __restrict__ bias, float* __restrict__ C)
{
    __shared__ __align__(16) __nv_bfloat16 sA[128][SAST];
    __shared__ __align__(16) __nv_bfloat16 sB[128][SAST];
    __shared__ float sbias[128];

    int tid = threadIdx.x, lane = tid & 31, wid = tid >> 5;
    int wm = wid >> 2, wn = wid & 3;            // warp grid 2(M) x 4(N)
    int n0 = blockIdx.x * 128, m0 = blockIdx.y * 128;

    for (int i = tid; i < 128; i += 256) {
        int n = n0 + i;
        sbias[i] = (n < OUTD) ? bias[n] : 0.f;
    }

    float acc[4][4][4];
    #pragma unroll
    for (int mt = 0; mt < 4; mt++)
        #pragma unroll
        for (int nt = 0; nt < 4; nt++)
            #pragma unroll
            for (int q = 0; q < 4; q++) acc[mt][nt][q] = 0.f;

    for (int ch = 0; ch < NCHUNK; ch++) {
        for (int i = tid; i < 1024; i += 256) {
            int r = i >> 3, c = (i & 7) * 8;
            *(uint4*)&sA[r][c] = *(const uint4*)(g_Abf + (size_t)(m0 + r) * KTOT + ch * KCH + c);
        }
        for (int i = tid; i < 1024; i += 256) {
            int r = i >> 3, c = (i & 7) * 8;
            *(uint4*)&sB[r][c] = *(const uint4*)(g_Bbf + (size_t)(n0 + r) * KTOT + ch * KCH + c);
        }
        __syncthreads();

        #pragma unroll
        for (int ks = 0; ks < 4; ks++) {
            uint32_t af[4][4], bf[2][4];
            #pragma unroll
            for (int mt = 0; mt < 4; mt++) {
                int row = wm * 64 + mt * 16 + (lane & 15);
                int col = ks * 16 + (lane >> 4) * 8;
                LDSM_X4(af[mt], smem_u32(&sA[row][col]));
            }
            #pragma unroll
            for (int p = 0; p < 2; p++) {
                int q = lane >> 3, rl = lane & 7;
                int nrow = wn * 32 + p * 16 + (q >> 1) * 8 + rl;
                int col = ks * 16 + (q & 1) * 8;
                LDSM_X4(bf[p], smem_u32(&sB[nrow][col]));
            }
            #pragma unroll
            for (int mt = 0; mt < 4; mt++)
                #pragma unroll
                for (int nt = 0; nt < 4; nt++)
                    MMA16816(acc[mt][nt], af[mt],
                             bf[nt >> 1][(nt & 1) * 2], bf[nt >> 1][(nt & 1) * 2 + 1]);
        }
        __syncthreads();
    }

    int gid = lane >> 2, tig = lane & 3;
    #pragma unroll
    for (int mt = 0; mt < 4; mt++) {
        int r0 = m0 + wm * 64 + mt * 16 + gid;
        int r1 = r0 + 8;
        #pragma unroll
        for (int nt = 0; nt < 4; nt++) {
            int lc = wn * 32 + nt * 8 + tig * 2;
            int c  = n0 + lc;
            if (c < OUTD) {
                float b0 = sbias[lc], b1 = sbias[lc + 1];
                if (r0 < NN) {
                    float2 v = make_float2(acc[mt][nt][0] + b0, acc[mt][nt][1] + b1);
                    *(float2*)(C + (size_t)r0 * OUTD + c) = v;
                }
                if (r1 < NN) {
                    float2 v = make_float2(acc[mt][nt][2] + b0, acc[mt][nt][3] + b1);
                    *(float2*)(C + (size_t)r1 * OUTD + c) = v;
                }
            }
        }
    }
}

// ---------------- launch ----------------
extern "C" void kernel_launch(void* const* d_in, const int* in_sizes, int n_in,
                              void* d_out, int out_size)
{
    const float* x        = (const float*)d_in[0];
    const float* hedge    = (const float*)d_in[1];
    const int*   node_idx = (const int*)  d_in[2];
    const int*   edge_idx = (const int*)  d_in[3];
    const float* lin_w    = (const float*)d_in[4];
    const float* lin_b    = (const float*)d_in[5];
    const float* s_ln_g   = (const float*)d_in[6];
    const float* s_ln_b   = (const float*)d_in[7];
    const float* sheaf_w  = (const float*)d_in[8];
    const float* sheaf_b  = (const float*)d_in[9];
    const float* c_ln_g   = (const float*)d_in[10];
    const float* c_ln_b   = (const float*)d_in[11];
    const float* conv_w   = (const float*)d_in[12];
    const float* conv_b   = (const float*)d_in[13];
    const float* conv_bias= (const float*)d_in[14];
    const float* lin2_w   = (const float*)d_in[15];
    const float* lin2_b   = (const float*)d_in[16];
    float* out = (float*)d_out;

    zero_counts_kernel<<<(NN + 255) / 256, 256>>>();
    proj_kernel<<<(NN + EE) / 8, 64>>>(x, hedge, lin_w, lin_b);
    sheaf_kernel<<<(NNZV + 255) / 256, 256>>>(node_idx, edge_idx,
                                              s_ln_g, s_ln_b, sheaf_w, sheaf_b);
    scan_kernel<<<2, 1024>>>();
    fill_kernel<<<(NNZV + 255) / 256, 256>>>(node_idx, edge_idx);
    prep_B_kernel<<<(B_ROWS_PAD * KTOT + 255) / 256, 256>>>(lin2_w);

    for (int l = 0; l < NLAY; l++) {
        h0_kernel<<<(NN * DH + 255) / 256, 256>>>(c_ln_g, c_ln_b, conv_w, conv_b, l);
        edge_gather_kernel<<<(EE * DH + 127) / 128, 128>>>();
        node_gather_fin_kernel<<<(NN * DH + 255) / 256, 256>>>(conv_bias, l);
    }

    dim3 grid((OUTD + 127) / 128, (NN + 127) / 128);   // 39 x 157
    lin2_mma_kernel<<<grid, 256>>>(lin2_b, out);
}

// round 8
// speedup vs baseline: 1.3564x; 1.1187x over previous
#include <cuda_runtime.h>
#include <cuda_bf16.h>
#include <math.h>
#include <stdint.h>

// ---------------- problem constants ----------------
#define NN    20000     // nodes
#define EE    5000      // hyperedges
#define NNZV  200000    // incidences
#define DH    6         // sheaf dim d
#define HID   9         // MLP hidden
#define FIN   256       // input features
#define OUTD  4968      // output dim
#define PROJ  54        // DH*HID
#define ROW12 12        // padded row stride (floats) for 9-wide rows
#define NLAY  2

// split-bf16 GEMM operand layout
#define KCH     64                   // bf16 per K-chunk (54 padded to 64)
#define NCHUNK  3                    // [hi|lo|hi] x [hi|hi|lo]
#define KTOT    (NCHUNK*KCH)         // 192
#define A_ROWS_PAD 20096             // 157*128
#define B_ROWS_PAD 5120              // >= 39*128

// ---------------- scratch (static device globals; no runtime alloc) ----------------
// Device globals are zero-initialized at module load; padding regions of
// g_Abf/g_Bbf are never written by any kernel -> stay zero across replays.
__device__ __align__(16) float g_xproj[NN * PROJ];
__device__ __align__(16) float g_xm[NN * ROW12];
__device__ __align__(16) float g_em[EE * ROW12];
__device__ __align__(16) float g_hsheaf[(size_t)NNZV * DH];
__device__ int   g_cnt_node[NN];
__device__ int   g_cnt_edge[EE];
__device__ int   g_noff[NN + 1];
__device__ int   g_eoff[EE + 1];
__device__ int   g_ncur[NN];
__device__ int   g_ecur[EE];
__device__ int   g_bsum_e[32];     // per-block partial sums (edges)
__device__ int   g_bsum_n[32];     // per-block partial sums (nodes)
__device__ __align__(8) int2 g_elist[NNZV];   // (k, node)
__device__ __align__(8) int2 g_nlist[NNZV];   // (k, edge)
__device__ __align__(16) float g_h0[(size_t)NN * DH * ROW12];
__device__ __align__(16) float g_m[(size_t)EE * DH * ROW12];
__device__ __align__(16) __nv_bfloat16 g_Abf[(size_t)A_ROWS_PAD * KTOT];  // 7.7 MB
__device__ __align__(16) __nv_bfloat16 g_Bbf[(size_t)B_ROWS_PAD * KTOT];  // 2.0 MB

// ---------------- zero counts + cursors ----------------
__global__ void zero_counts_kernel() {
    int i = blockIdx.x * blockDim.x + threadIdx.x;
    if (i < NN) { g_cnt_node[i] = 0; g_ncur[i] = 0; }
    if (i < EE) { g_cnt_edge[i] = 0; g_ecur[i] = 0; }
}

// ---------------- input projection + per-row mean over d ----------------
__global__ void proj_kernel(const float* __restrict__ x,
                            const float* __restrict__ ha,
                            const float* __restrict__ W,
                            const float* __restrict__ b)
{
    __shared__ float sx[8][FIN];
    __shared__ float sout[8][PROJ];
    int r0 = blockIdx.x * 8;
    int t  = threadIdx.x;

    #pragma unroll
    for (int rr = 0; rr < 8; rr++) {
        int r = r0 + rr;
        if (r >= NN + EE) break;
        const float* src = (r < NN) ? (x + (size_t)r * FIN) : (ha + (size_t)(r - NN) * FIN);
        for (int c = t; c < FIN; c += 64) sx[rr][c] = src[c];
    }
    __syncthreads();

    if (t < PROJ) {
        float acc[8];
        float bt = b[t];
        #pragma unroll
        for (int rr = 0; rr < 8; rr++) acc[rr] = bt;
        #pragma unroll 4
        for (int c = 0; c < FIN; c++) {
            float w = W[c * PROJ + t];
            #pragma unroll
            for (int rr = 0; rr < 8; rr++) acc[rr] += w * sx[rr][c];
        }
        #pragma unroll
        for (int rr = 0; rr < 8; rr++) {
            int r = r0 + rr;
            if (r >= NN + EE) break;
            if (r < NN) g_xproj[(size_t)r * PROJ + t] = acc[rr];
            sout[rr][t] = acc[rr];
        }
    }
    __syncthreads();

    if (t < HID) {
        #pragma unroll
        for (int rr = 0; rr < 8; rr++) {
            int r = r0 + rr;
            if (r >= NN + EE) break;
            float s = 0.f;
            #pragma unroll
            for (int j = 0; j < DH; j++) s += sout[rr][j * HID + t];
            s *= (1.0f / DH);
            if (r < NN) g_xm[(size_t)r * ROW12 + t] = s;
            else        g_em[(size_t)(r - NN) * ROW12 + t] = s;
        }
    }
}

// ---------------- sheaf builder (alpha + degree counts) ----------------
__global__ void sheaf_kernel(const int* __restrict__ ni, const int* __restrict__ ei,
                             const float* __restrict__ lng, const float* __restrict__ lnb,
                             const float* __restrict__ sw,  const float* __restrict__ sb)
{
    __shared__ float s_sw[2 * HID * DH];
    __shared__ float s_sb[DH];
    __shared__ float s_g[2 * HID], s_b[2 * HID];
    int t = threadIdx.x;
    if (t < 2 * HID * DH) s_sw[t] = sw[t];
    if (t < DH) s_sb[t] = sb[t];
    if (t < 2 * HID) { s_g[t] = lng[t]; s_b[t] = lnb[t]; }
    __syncthreads();

    int k = blockIdx.x * blockDim.x + threadIdx.x;
    if (k >= NNZV) return;
    int n = ni[k], e = ei[k];

    float v[2 * HID];
    {
        const float4 a0 = *(const float4*)(g_xm + (size_t)n * ROW12);
        const float4 a1 = *(const float4*)(g_xm + (size_t)n * ROW12 + 4);
        v[0]=a0.x; v[1]=a0.y; v[2]=a0.z; v[3]=a0.w;
        v[4]=a1.x; v[5]=a1.y; v[6]=a1.z; v[7]=a1.w;
        v[8] = g_xm[(size_t)n * ROW12 + 8];
        const float4 b0 = *(const float4*)(g_em + (size_t)e * ROW12);
        const float4 b1 = *(const float4*)(g_em + (size_t)e * ROW12 + 4);
        v[9]=b0.x; v[10]=b0.y; v[11]=b0.z; v[12]=b0.w;
        v[13]=b1.x; v[14]=b1.y; v[15]=b1.z; v[16]=b1.w;
        v[17] = g_em[(size_t)e * ROW12 + 8];
    }
    float mean = 0.f;
    #pragma unroll
    for (int i = 0; i < 18; i++) mean += v[i];
    mean *= (1.0f / 18.0f);
    float var = 0.f;
    #pragma unroll
    for (int i = 0; i < 18; i++) { float d = v[i] - mean; var += d * d; }
    var *= (1.0f / 18.0f);
    float rs = rsqrtf(var + 1e-5f);
    float y[18];
    #pragma unroll
    for (int i = 0; i < 18; i++) y[i] = (v[i] - mean) * rs * s_g[i] + s_b[i];

    #pragma unroll
    for (int j = 0; j < DH; j++) {
        float z = s_sb[j];
        #pragma unroll
        for (int i = 0; i < 18; i++) z += y[i] * s_sw[i * DH + j];
        float h = 1.0f / (1.0f + __expf(-z));
        g_hsheaf[(size_t)k * DH + j] = h;
    }
    atomicAdd(&g_cnt_node[n], 1);
    atomicAdd(&g_cnt_edge[e], 1);
}

// ---------------- hierarchical scan (3 stages) ----------------
// stage 1: 1024-element blocks, warp-shuffle scan; blockIdx.y: 0=edges 1=nodes
__global__ void scan1_kernel()
{
    __shared__ int wsum[32];
    const int* cnt = (blockIdx.y == 0) ? g_cnt_edge : g_cnt_node;
    int* off       = (blockIdx.y == 0) ? g_eoff : g_noff;
    int* bsum      = (blockIdx.y == 0) ? g_bsum_e : g_bsum_n;
    int len        = (blockIdx.y == 0) ? EE : NN;
    int nblk       = (len + 1023) >> 10;
    if (blockIdx.x >= nblk) return;

    int t = threadIdx.x, lane = t & 31, w = t >> 5;
    int i = blockIdx.x * 1024 + t;
    int v = (i < len) ? cnt[i] : 0;

    int sv = v;   // inclusive warp scan
    #pragma unroll
    for (int d = 1; d < 32; d <<= 1) {
        int u = __shfl_up_sync(0xFFFFFFFF, sv, d);
        if (lane >= d) sv += u;
    }
    if (lane == 31) wsum[w] = sv;
    __syncthreads();
    if (w == 0) {
        int ws = wsum[lane];
        #pragma unroll
        for (int d = 1; d < 32; d <<= 1) {
            int u = __shfl_up_sync(0xFFFFFFFF, ws, d);
            if (lane >= d) ws += u;
        }
        wsum[lane] = ws;
    }
    __syncthreads();
    int wbase = (w > 0) ? wsum[w - 1] : 0;
    if (i < len) off[i] = wbase + sv - v;           // exclusive within block
    if (t == 1023) bsum[blockIdx.x] = wbase + sv;   // block total
}

// stage 2: one block scans both partial arrays (<=32 each) exclusively
__global__ void scan2_kernel()
{
    int lane = threadIdx.x & 31;
    int nb_e = (EE + 1023) >> 10, nb_n = (NN + 1023) >> 10;
    int* bsum = (threadIdx.x < 32) ? g_bsum_e : g_bsum_n;
    int nb    = (threadIdx.x < 32) ? nb_e : nb_n;
    int v = (lane < nb) ? bsum[lane] : 0;
    int sv = v;
    #pragma unroll
    for (int d = 1; d < 32; d <<= 1) {
        int u = __shfl_up_sync(0xFFFFFFFF, sv, d);
        if (lane >= d) sv += u;
    }
    if (lane < nb) bsum[lane] = sv - v;   // exclusive
    if (lane == 31) {                      // total
        if (threadIdx.x < 32) g_eoff[EE] = sv;
        else                  g_noff[NN] = sv;
    }
}

// stage 3: add block offsets
__global__ void scan3_kernel()
{
    int* off        = (blockIdx.y == 0) ? g_eoff : g_noff;
    const int* bsum = (blockIdx.y == 0) ? g_bsum_e : g_bsum_n;
    int len         = (blockIdx.y == 0) ? EE : NN;
    int i = blockIdx.x * 1024 + threadIdx.x;
    if (i < len) off[i] += bsum[blockIdx.x];
}

// ---------------- CSR fill ----------------
__global__ void fill_kernel(const int* __restrict__ ni, const int* __restrict__ ei)
{
    int k = blockIdx.x * blockDim.x + threadIdx.x;
    if (k >= NNZV) return;
    int n = ni[k], e = ei[k];
    int pe = atomicAdd(&g_ecur[e], 1);
    g_elist[g_eoff[e] + pe] = make_int2(k, n);
    int pn = atomicAdd(&g_ncur[n], 1);
    g_nlist[g_noff[n] + pn] = make_int2(k, e);
}

// ---------------- per-layer: h0 = LN(x) @ conv_w[l] + conv_b[l] ----------------
__global__ void h0_kernel(const float* __restrict__ lng, const float* __restrict__ lnb,
                          const float* __restrict__ W,   const float* __restrict__ cb,
                          int l)
{
    __shared__ float sW[HID * HID];
    __shared__ float sg[HID], sb2[HID], scb[HID];
    int t = threadIdx.x;
    if (t < HID * HID) sW[t] = W[l * HID * HID + t];
    if (t < HID) { sg[t] = lng[l * HID + t]; sb2[t] = lnb[l * HID + t]; scb[t] = cb[l * HID + t]; }
    __syncthreads();

    int r = blockIdx.x * blockDim.x + threadIdx.x;
    if (r >= NN * DH) return;

    float v[HID];
    #pragma unroll
    for (int h = 0; h < HID; h++) v[h] = g_xproj[(size_t)r * HID + h];
    float mean = 0.f;
    #pragma unroll
    for (int h = 0; h < HID; h++) mean += v[h];
    mean *= (1.0f / HID);
    float var = 0.f;
    #pragma unroll
    for (int h = 0; h < HID; h++) { float d = v[h] - mean; var += d * d; }
    var *= (1.0f / HID);
    float rs = rsqrtf(var + 1e-5f);
    float y[HID];
    #pragma unroll
    for (int h = 0; h < HID; h++) y[h] = (v[h] - mean) * rs * sg[h] + sb2[h];

    #pragma unroll
    for (int c = 0; c < HID; c++) {
        float acc = scb[c];
        #pragma unroll
        for (int h = 0; h < HID; h++) acc += y[h] * sW[h * HID + c];
        g_h0[(size_t)r * ROW12 + c] = acc;
    }
}

// ---------------- warp-per-edge gather: m[e*d+j] = Be * sum alpha(k,j) h0[n*d+j] -------
// lanes 0..29: j = lane%6, q = lane/6 (5 incidence groups); 4-shuffle reduction.
__global__ void edge_gather_kernel()
{
    int w = (blockIdx.x * blockDim.x + threadIdx.x) >> 5;
    int lane = threadIdx.x & 31;
    if (w >= EE) return;
    int s = g_eoff[w], t = g_eoff[w + 1];
    float be = (t > s) ? (1.0f / (float)(t - s)) : 0.f;
    int j = lane % DH, q = lane / DH;
    bool act = (lane < 30);

    float a[HID];
    #pragma unroll
    for (int h = 0; h < HID; h++) a[h] = 0.f;

    if (act) {
        for (int p = s + q; p < t; p += 5) {
            int2 kn = g_elist[p];
            float al = g_hsheaf[(size_t)kn.x * DH + j];
            const float* src = g_h0 + ((size_t)kn.y * DH + j) * ROW12;
            float4 v0 = *(const float4*)src;
            float4 v1 = *(const float4*)(src + 4);
            float  v2 = src[8];
            a[0] += al * v0.x; a[1] += al * v0.y; a[2] += al * v0.z; a[3] += al * v0.w;
            a[4] += al * v1.x; a[5] += al * v1.y; a[6] += al * v1.z; a[7] += al * v1.w;
            a[8] += al * v2;
        }
    }
    #pragma unroll
    for (int h = 0; h < HID; h++) {
        float v = a[h];
        float v6  = __shfl_down_sync(0xFFFFFFFF, v, 6);
        float v12 = __shfl_down_sync(0xFFFFFFFF, v, 12);
        float v18 = __shfl_down_sync(0xFFFFFFFF, v, 18);
        float v24 = __shfl_down_sync(0xFFFFFFFF, v, 24);
        a[h] = v + v6 + v12 + v18 + v24;
    }
    if (lane < DH) {
        float* dst = g_m + ((size_t)w * DH + j) * ROW12;
        *(float4*)dst       = make_float4(a[0] * be, a[1] * be, a[2] * be, a[3] * be);
        *(float4*)(dst + 4) = make_float4(a[4] * be, a[5] * be, a[6] * be, a[7] * be);
        dst[8] = a[8] * be;
    }
}

// ---------------- warp-per-node gather + finalize (+ bf16 A emit on last layer) --------
__global__ void node_gather_fin_kernel(const float* __restrict__ cbias, int l)
{
    int w = (blockIdx.x * blockDim.x + threadIdx.x) >> 5;
    int lane = threadIdx.x & 31;
    if (w >= NN) return;
    int s = g_noff[w], t = g_noff[w + 1];
    float dv = (t > s) ? (1.0f / (float)(t - s)) : 0.f;
    int j = lane % DH, q = lane / DH;
    bool act = (lane < 30);

    float a[HID];
    #pragma unroll
    for (int h = 0; h < HID; h++) a[h] = 0.f;

    if (act) {
        for (int p = s + q; p < t; p += 5) {
            int2 ke = g_nlist[p];
            float al = g_hsheaf[(size_t)ke.x * DH + j];
            const float* src = g_m + ((size_t)ke.y * DH + j) * ROW12;
            float4 v0 = *(const float4*)src;
            float4 v1 = *(const float4*)(src + 4);
            float  v2 = src[8];
            a[0] += al * v0.x; a[1] += al * v0.y; a[2] += al * v0.z; a[3] += al * v0.w;
            a[4] += al * v1.x; a[5] += al * v1.y; a[6] += al * v1.z; a[7] += al * v1.w;
            a[8] += al * v2;
        }
    }
    #pragma unroll
    for (int h = 0; h < HID; h++) {
        float v = a[h];
        float v6  = __shfl_down_sync(0xFFFFFFFF, v, 6);
        float v12 = __shfl_down_sync(0xFFFFFFFF, v, 12);
        float v18 = __shfl_down_sync(0xFFFFFFFF, v, 18);
        float v24 = __shfl_down_sync(0xFFFFFFFF, v, 24);
        a[h] = v + v6 + v12 + v18 + v24;
    }

    if (lane < DH) {
        size_t idx = (size_t)w * DH + j;
        const float* h0r = g_h0 + idx * ROW12;
        float o[HID];
        #pragma unroll
        for (int h = 0; h < HID; h++)
            o[h] = a[h] * dv + h0r[h] + cbias[l * HID + h];

        if (l == 0) {
            #pragma unroll
            for (int h = 0; h < HID; h++) {
                float v = o[h];
                v = (v > 0.f) ? v : expm1f(v);   // ELU
                g_xproj[idx * HID + h] = v;
            }
        } else {
            __nv_bfloat16* arow = g_Abf + (size_t)w * KTOT + j * HID;
            #pragma unroll
            for (int h = 0; h < HID; h++) {
                float v = o[h];
                __nv_bfloat16 hi = __float2bfloat16(v);
                __nv_bfloat16 lo = __float2bfloat16(v - __bfloat162float(hi));
                arow[h]            = hi;
                arow[KCH + h]      = lo;
                arow[2 * KCH + h]  = hi;
            }
        }
    }
}

// ---------------- B' prep: [B_hi | B_hi | B_lo], B[n][k] = W2[k][n] ----------------
__global__ void prep_B_kernel(const float* __restrict__ W2)
{
    int idx = blockIdx.x * blockDim.x + threadIdx.x;
    if (idx >= B_ROWS_PAD * KTOT) return;
    int n = idx / KTOT, k = idx - n * KTOT;
    int region = k >> 6, j = k & 63;
    __nv_bfloat16 o = __float2bfloat16(0.f);
    if (n < OUTD && j < PROJ) {
        float a = W2[(size_t)j * OUTD + n];
        __nv_bfloat16 h = __float2bfloat16(a);
        if (region == 2) o = __float2bfloat16(a - __bfloat162float(h));
        else             o = h;
    }
    g_Bbf[idx] = o;
}

// ---------------- HMMA lin2 GEMM (unchanged from R5/R6 passing version) ----------------
#define LDSM_X4(r, addr) \
    asm volatile("ldmatrix.sync.aligned.m8n8.x4.shared.b16 {%0,%1,%2,%3}, [%4];" \
        : "=r"((r)[0]), "=r"((r)[1]), "=r"((r)[2]), "=r"((r)[3]) : "r"(addr))
#define MMA16816(d, a, b0, b1) \
    asm volatile("mma.sync.aligned.m16n8k16.row.col.f32.bf16.bf16.f32 " \
        "{%0,%1,%2,%3}, {%4,%5,%6,%7}, {%8,%9}, {%0,%1,%2,%3};" \
        : "+f"((d)[0]), "+f"((d)[1]), "+f"((d)[2]), "+f"((d)[3]) \
        : "r"((a)[0]), "r"((a)[1]), "r"((a)[2]), "r"((a)[3]), "r"(b0), "r"(b1))

__device__ __forceinline__ uint32_t smem_u32(const void* p) {
    uint32_t a;
    asm("{ .reg .u64 t; cvta.to.shared.u64 t, %1; cvt.u32.u64 %0, t; }" : "=r"(a) : "l"(p));
    return a;
}

#define SAST 72   // smem bf16 stride per row

__global__ void __launch_bounds__(256, 2)
lin2_mma_kernel(const float* __restrict__ bias, float* __restrict__ C)
{
    __shared__ __align__(16) __nv_bfloat16 sA[128][SAST];
    __shared__ __align__(16) __nv_bfloat16 sB[128][SAST];
    __shared__ float sbias[128];

    int tid = threadIdx.x, lane = tid & 31, wid = tid >> 5;
    int wm = wid >> 2, wn = wid & 3;            // warp grid 2(M) x 4(N)
    int n0 = blockIdx.x * 128, m0 = blockIdx.y * 128;

    for (int i = tid; i < 128; i += 256) {
        int n = n0 + i;
        sbias[i] = (n < OUTD) ? bias[n] : 0.f;
    }

    float acc[4][4][4];
    #pragma unroll
    for (int mt = 0; mt < 4; mt++)
        #pragma unroll
        for (int nt = 0; nt < 4; nt++)
            #pragma unroll
            for (int q = 0; q < 4; q++) acc[mt][nt][q] = 0.f;

    for (int ch = 0; ch < NCHUNK; ch++) {
        for (int i = tid; i < 1024; i += 256) {
            int r = i >> 3, c = (i & 7) * 8;
            *(uint4*)&sA[r][c] = *(const uint4*)(g_Abf + (size_t)(m0 + r) * KTOT + ch * KCH + c);
        }
        for (int i = tid; i < 1024; i += 256) {
            int r = i >> 3, c = (i & 7) * 8;
            *(uint4*)&sB[r][c] = *(const uint4*)(g_Bbf + (size_t)(n0 + r) * KTOT + ch * KCH + c);
        }
        __syncthreads();

        #pragma unroll
        for (int ks = 0; ks < 4; ks++) {
            uint32_t af[4][4], bf[2][4];
            #pragma unroll
            for (int mt = 0; mt < 4; mt++) {
                int row = wm * 64 + mt * 16 + (lane & 15);
                int col = ks * 16 + (lane >> 4) * 8;
                LDSM_X4(af[mt], smem_u32(&sA[row][col]));
            }
            #pragma unroll
            for (int p = 0; p < 2; p++) {
                int q = lane >> 3, rl = lane & 7;
                int nrow = wn * 32 + p * 16 + (q >> 1) * 8 + rl;
                int col = ks * 16 + (q & 1) * 8;
                LDSM_X4(bf[p], smem_u32(&sB[nrow][col]));
            }
            #pragma unroll
            for (int mt = 0; mt < 4; mt++)
                #pragma unroll
                for (int nt = 0; nt < 4; nt++)
                    MMA16816(acc[mt][nt], af[mt],
                             bf[nt >> 1][(nt & 1) * 2], bf[nt >> 1][(nt & 1) * 2 + 1]);
        }
        __syncthreads();
    }

    int gid = lane >> 2, tig = lane & 3;
    #pragma unroll
    for (int mt = 0; mt < 4; mt++) {
        int r0 = m0 + wm * 64 + mt * 16 + gid;
        int r1 = r0 + 8;
        #pragma unroll
        for (int nt = 0; nt < 4; nt++) {
            int lc = wn * 32 + nt * 8 + tig * 2;
            int c  = n0 + lc;
            if (c < OUTD) {
                float b0 = sbias[lc], b1 = sbias[lc + 1];
                if (r0 < NN) {
                    float2 v = make_float2(acc[mt][nt][0] + b0, acc[mt][nt][1] + b1);
                    *(float2*)(C + (size_t)r0 * OUTD + c) = v;
                }
                if (r1 < NN) {
                    float2 v = make_float2(acc[mt][nt][2] + b0, acc[mt][nt][3] + b1);
                    *(float2*)(C + (size_t)r1 * OUTD + c) = v;
                }
            }
        }
    }
}

// ---------------- launch ----------------
extern "C" void kernel_launch(void* const* d_in, const int* in_sizes, int n_in,
                              void* d_out, int out_size)
{
    const float* x        = (const float*)d_in[0];
    const float* hedge    = (const float*)d_in[1];
    const int*   node_idx = (const int*)  d_in[2];
    const int*   edge_idx = (const int*)  d_in[3];
    const float* lin_w    = (const float*)d_in[4];
    const float* lin_b    = (const float*)d_in[5];
    const float* s_ln_g   = (const float*)d_in[6];
    const float* s_ln_b   = (const float*)d_in[7];
    const float* sheaf_w  = (const float*)d_in[8];
    const float* sheaf_b  = (const float*)d_in[9];
    const float* c_ln_g   = (const float*)d_in[10];
    const float* c_ln_b   = (const float*)d_in[11];
    const float* conv_w   = (const float*)d_in[12];
    const float* conv_b   = (const float*)d_in[13];
    const float* conv_bias= (const float*)d_in[14];
    const float* lin2_w   = (const float*)d_in[15];
    const float* lin2_b   = (const float*)d_in[16];
    float* out = (float*)d_out;

    zero_counts_kernel<<<(NN + 255) / 256, 256>>>();
    proj_kernel<<<(NN + EE) / 8, 64>>>(x, hedge, lin_w, lin_b);
    sheaf_kernel<<<(NNZV + 255) / 256, 256>>>(node_idx, edge_idx,
                                              s_ln_g, s_ln_b, sheaf_w, sheaf_b);
    {
        dim3 g1((NN + 1023) / 1024, 2);
        scan1_kernel<<<g1, 1024>>>();
        scan2_kernel<<<1, 64>>>();
        scan3_kernel<<<g1, 1024>>>();
    }
    fill_kernel<<<(NNZV + 255) / 256, 256>>>(node_idx, edge_idx);
    prep_B_kernel<<<(B_ROWS_PAD * KTOT + 255) / 256, 256>>>(lin2_w);

    for (int l = 0; l < NLAY; l++) {
        h0_kernel<<<(NN * DH + 255) / 256, 256>>>(c_ln_g, c_ln_b, conv_w, conv_b, l);
        edge_gather_kernel<<<(EE * 32 + 255) / 256, 256>>>();
        node_gather_fin_kernel<<<(NN * 32 + 255) / 256, 256>>>(conv_bias, l);
    }

    dim3 grid((OUTD + 127) / 128, (NN + 127) / 128);   // 39 x 157
    lin2_mma_kernel<<<grid, 256>>>(lin2_b, out);
}

// round 9
// speedup vs baseline: 1.6960x; 1.2504x over previous
#include <cuda_runtime.h>
#include <cuda_bf16.h>
#include <math.h>
#include <stdint.h>

// ---------------- problem constants ----------------
#define NN    20000     // nodes
#define EE    5000      // hyperedges
#define NNZV  200000    // incidences
#define DH    6         // sheaf dim d
#define HID   9         // MLP hidden
#define FIN   256       // input features
#define OUTD  4968      // output dim
#define PROJ  54        // DH*HID
#define ROW12 12        // padded row stride (floats) for 9-wide rows
#define NLAY  2

// split-bf16 GEMM operand layout
#define KCH     64                   // bf16 per K-chunk (54 padded to 64)
#define NCHUNK  3                    // [hi|lo|hi] x [hi|hi|lo]
#define KTOT    (NCHUNK*KCH)         // 192
#define A_ROWS_PAD 20096             // 157*128
#define B_ROWS_PAD 5120              // 20*256

// ---------------- scratch (static device globals; no runtime alloc) ----------------
// Device globals are zero-initialized at module load; padding regions of
// g_Abf/g_Bbf are never written by any kernel -> stay zero across replays.
__device__ __align__(16) float g_xproj[NN * PROJ];
__device__ __align__(16) float g_xm[NN * ROW12];
__device__ __align__(16) float g_em[EE * ROW12];
__device__ __align__(16) float g_hsheaf[(size_t)NNZV * DH];
__device__ int   g_cnt_node[NN];
__device__ int   g_cnt_edge[EE];
__device__ int   g_noff[NN + 1];
__device__ int   g_eoff[EE + 1];
__device__ int   g_ncur[NN];
__device__ int   g_ecur[EE];
__device__ int   g_bsum_e[32];
__device__ int   g_bsum_n[32];
__device__ __align__(8) int2 g_elist[NNZV];   // (k, node)
__device__ __align__(8) int2 g_nlist[NNZV];   // (k, edge)
__device__ __align__(16) float g_h0[(size_t)NN * DH * ROW12];
__device__ __align__(16) float g_m[(size_t)EE * DH * ROW12];
__device__ __align__(16) __nv_bfloat16 g_Abf[(size_t)A_ROWS_PAD * KTOT];  // 7.7 MB
__device__ __align__(16) __nv_bfloat16 g_Bbf[(size_t)B_ROWS_PAD * KTOT];  // 2.0 MB

// ---------------- zero counts + cursors ----------------
__global__ void zero_counts_kernel() {
    int i = blockIdx.x * blockDim.x + threadIdx.x;
    if (i < NN) { g_cnt_node[i] = 0; g_ncur[i] = 0; }
    if (i < EE) { g_cnt_edge[i] = 0; g_ecur[i] = 0; }
}

// ---------------- input projection + per-row mean over d ----------------
__global__ void proj_kernel(const float* __restrict__ x,
                            const float* __restrict__ ha,
                            const float* __restrict__ W,
                            const float* __restrict__ b)
{
    __shared__ float sx[8][FIN];
    __shared__ float sout[8][PROJ];
    int r0 = blockIdx.x * 8;
    int t  = threadIdx.x;

    #pragma unroll
    for (int rr = 0; rr < 8; rr++) {
        int r = r0 + rr;
        if (r >= NN + EE) break;
        const float* src = (r < NN) ? (x + (size_t)r * FIN) : (ha + (size_t)(r - NN) * FIN);
        for (int c = t; c < FIN; c += 64) sx[rr][c] = src[c];
    }
    __syncthreads();

    if (t < PROJ) {
        float acc[8];
        float bt = b[t];
        #pragma unroll
        for (int rr = 0; rr < 8; rr++) acc[rr] = bt;
        #pragma unroll 4
        for (int c = 0; c < FIN; c++) {
            float w = W[c * PROJ + t];
            #pragma unroll
            for (int rr = 0; rr < 8; rr++) acc[rr] += w * sx[rr][c];
        }
        #pragma unroll
        for (int rr = 0; rr < 8; rr++) {
            int r = r0 + rr;
            if (r >= NN + EE) break;
            if (r < NN) g_xproj[(size_t)r * PROJ + t] = acc[rr];
            sout[rr][t] = acc[rr];
        }
    }
    __syncthreads();

    if (t < HID) {
        #pragma unroll
        for (int rr = 0; rr < 8; rr++) {
            int r = r0 + rr;
            if (r >= NN + EE) break;
            float s = 0.f;
            #pragma unroll
            for (int j = 0; j < DH; j++) s += sout[rr][j * HID + t];
            s *= (1.0f / DH);
            if (r < NN) g_xm[(size_t)r * ROW12 + t] = s;
            else        g_em[(size_t)(r - NN) * ROW12 + t] = s;
        }
    }
}

// ---------------- sheaf builder (alpha + degree counts) ----------------
__global__ void sheaf_kernel(const int* __restrict__ ni, const int* __restrict__ ei,
                             const float* __restrict__ lng, const float* __restrict__ lnb,
                             const float* __restrict__ sw,  const float* __restrict__ sb)
{
    __shared__ float s_sw[2 * HID * DH];
    __shared__ float s_sb[DH];
    __shared__ float s_g[2 * HID], s_b[2 * HID];
    int t = threadIdx.x;
    if (t < 2 * HID * DH) s_sw[t] = sw[t];
    if (t < DH) s_sb[t] = sb[t];
    if (t < 2 * HID) { s_g[t] = lng[t]; s_b[t] = lnb[t]; }
    __syncthreads();

    int k = blockIdx.x * blockDim.x + threadIdx.x;
    if (k >= NNZV) return;
    int n = ni[k], e = ei[k];

    float v[2 * HID];
    {
        const float4 a0 = *(const float4*)(g_xm + (size_t)n * ROW12);
        const float4 a1 = *(const float4*)(g_xm + (size_t)n * ROW12 + 4);
        v[0]=a0.x; v[1]=a0.y; v[2]=a0.z; v[3]=a0.w;
        v[4]=a1.x; v[5]=a1.y; v[6]=a1.z; v[7]=a1.w;
        v[8] = g_xm[(size_t)n * ROW12 + 8];
        const float4 b0 = *(const float4*)(g_em + (size_t)e * ROW12);
        const float4 b1 = *(const float4*)(g_em + (size_t)e * ROW12 + 4);
        v[9]=b0.x; v[10]=b0.y; v[11]=b0.z; v[12]=b0.w;
        v[13]=b1.x; v[14]=b1.y; v[15]=b1.z; v[16]=b1.w;
        v[17] = g_em[(size_t)e * ROW12 + 8];
    }
    float mean = 0.f;
    #pragma unroll
    for (int i = 0; i < 18; i++) mean += v[i];
    mean *= (1.0f / 18.0f);
    float var = 0.f;
    #pragma unroll
    for (int i = 0; i < 18; i++) { float d = v[i] - mean; var += d * d; }
    var *= (1.0f / 18.0f);
    float rs = rsqrtf(var + 1e-5f);
    float y[18];
    #pragma unroll
    for (int i = 0; i < 18; i++) y[i] = (v[i] - mean) * rs * s_g[i] + s_b[i];

    #pragma unroll
    for (int j = 0; j < DH; j++) {
        float z = s_sb[j];
        #pragma unroll
        for (int i = 0; i < 18; i++) z += y[i] * s_sw[i * DH + j];
        float h = 1.0f / (1.0f + __expf(-z));
        g_hsheaf[(size_t)k * DH + j] = h;
    }
    atomicAdd(&g_cnt_node[n], 1);
    atomicAdd(&g_cnt_edge[e], 1);
}

// ---------------- hierarchical scan (3 stages) ----------------
__global__ void scan1_kernel()
{
    __shared__ int wsum[32];
    const int* cnt = (blockIdx.y == 0) ? g_cnt_edge : g_cnt_node;
    int* off       = (blockIdx.y == 0) ? g_eoff : g_noff;
    int* bsum      = (blockIdx.y == 0) ? g_bsum_e : g_bsum_n;
    int len        = (blockIdx.y == 0) ? EE : NN;
    int nblk       = (len + 1023) >> 10;
    if (blockIdx.x >= nblk) return;

    int t = threadIdx.x, lane = t & 31, w = t >> 5;
    int i = blockIdx.x * 1024 + t;
    int v = (i < len) ? cnt[i] : 0;

    int sv = v;
    #pragma unroll
    for (int d = 1; d < 32; d <<= 1) {
        int u = __shfl_up_sync(0xFFFFFFFF, sv, d);
        if (lane >= d) sv += u;
    }
    if (lane == 31) wsum[w] = sv;
    __syncthreads();
    if (w == 0) {
        int ws = wsum[lane];
        #pragma unroll
        for (int d = 1; d < 32; d <<= 1) {
            int u = __shfl_up_sync(0xFFFFFFFF, ws, d);
            if (lane >= d) ws += u;
        }
        wsum[lane] = ws;
    }
    __syncthreads();
    int wbase = (w > 0) ? wsum[w - 1] : 0;
    if (i < len) off[i] = wbase + sv - v;
    if (t == 1023) bsum[blockIdx.x] = wbase + sv;
}

__global__ void scan2_kernel()
{
    int lane = threadIdx.x & 31;
    int nb_e = (EE + 1023) >> 10, nb_n = (NN + 1023) >> 10;
    int* bsum = (threadIdx.x < 32) ? g_bsum_e : g_bsum_n;
    int nb    = (threadIdx.x < 32) ? nb_e : nb_n;
    int v = (lane < nb) ? bsum[lane] : 0;
    int sv = v;
    #pragma unroll
    for (int d = 1; d < 32; d <<= 1) {
        int u = __shfl_up_sync(0xFFFFFFFF, sv, d);
        if (lane >= d) sv += u;
    }
    if (lane < nb) bsum[lane] = sv - v;
    if (lane == 31) {
        if (threadIdx.x < 32) g_eoff[EE] = sv;
        else                  g_noff[NN] = sv;
    }
}

__global__ void scan3_kernel()
{
    int* off        = (blockIdx.y == 0) ? g_eoff : g_noff;
    const int* bsum = (blockIdx.y == 0) ? g_bsum_e : g_bsum_n;
    int len         = (blockIdx.y == 0) ? EE : NN;
    int i = blockIdx.x * 1024 + threadIdx.x;
    if (i < len) off[i] += bsum[blockIdx.x];
}

// ---------------- CSR fill ----------------
__global__ void fill_kernel(const int* __restrict__ ni, const int* __restrict__ ei)
{
    int k = blockIdx.x * blockDim.x + threadIdx.x;
    if (k >= NNZV) return;
    int n = ni[k], e = ei[k];
    int pe = atomicAdd(&g_ecur[e], 1);
    g_elist[g_eoff[e] + pe] = make_int2(k, n);
    int pn = atomicAdd(&g_ncur[n], 1);
    g_nlist[g_noff[n] + pn] = make_int2(k, e);
}

// ---------------- per-layer: h0 = LN(x) @ conv_w[l] + conv_b[l] ----------------
__global__ void h0_kernel(const float* __restrict__ lng, const float* __restrict__ lnb,
                          const float* __restrict__ W,   const float* __restrict__ cb,
                          int l)
{
    __shared__ float sW[HID * HID];
    __shared__ float sg[HID], sb2[HID], scb[HID];
    int t = threadIdx.x;
    if (t < HID * HID) sW[t] = W[l * HID * HID + t];
    if (t < HID) { sg[t] = lng[l * HID + t]; sb2[t] = lnb[l * HID + t]; scb[t] = cb[l * HID + t]; }
    __syncthreads();

    int r = blockIdx.x * blockDim.x + threadIdx.x;
    if (r >= NN * DH) return;

    float v[HID];
    #pragma unroll
    for (int h = 0; h < HID; h++) v[h] = g_xproj[(size_t)r * HID + h];
    float mean = 0.f;
    #pragma unroll
    for (int h = 0; h < HID; h++) mean += v[h];
    mean *= (1.0f / HID);
    float var = 0.f;
    #pragma unroll
    for (int h = 0; h < HID; h++) { float d = v[h] - mean; var += d * d; }
    var *= (1.0f / HID);
    float rs = rsqrtf(var + 1e-5f);
    float y[HID];
    #pragma unroll
    for (int h = 0; h < HID; h++) y[h] = (v[h] - mean) * rs * sg[h] + sb2[h];

    #pragma unroll
    for (int c = 0; c < HID; c++) {
        float acc = scb[c];
        #pragma unroll
        for (int h = 0; h < HID; h++) acc += y[h] * sW[h * HID + c];
        g_h0[(size_t)r * ROW12 + c] = acc;
    }
}

// ---------------- warp-per-edge gather ----------------
__global__ void edge_gather_kernel()
{
    int w = (blockIdx.x * blockDim.x + threadIdx.x) >> 5;
    int lane = threadIdx.x & 31;
    if (w >= EE) return;
    int s = g_eoff[w], t = g_eoff[w + 1];
    float be = (t > s) ? (1.0f / (float)(t - s)) : 0.f;
    int j = lane % DH, q = lane / DH;
    bool act = (lane < 30);

    float a[HID];
    #pragma unroll
    for (int h = 0; h < HID; h++) a[h] = 0.f;

    if (act) {
        for (int p = s + q; p < t; p += 5) {
            int2 kn = g_elist[p];
            float al = g_hsheaf[(size_t)kn.x * DH + j];
            const float* src = g_h0 + ((size_t)kn.y * DH + j) * ROW12;
            float4 v0 = *(const float4*)src;
            float4 v1 = *(const float4*)(src + 4);
            float  v2 = src[8];
            a[0] += al * v0.x; a[1] += al * v0.y; a[2] += al * v0.z; a[3] += al * v0.w;
            a[4] += al * v1.x; a[5] += al * v1.y; a[6] += al * v1.z; a[7] += al * v1.w;
            a[8] += al * v2;
        }
    }
    #pragma unroll
    for (int h = 0; h < HID; h++) {
        float v = a[h];
        float v6  = __shfl_down_sync(0xFFFFFFFF, v, 6);
        float v12 = __shfl_down_sync(0xFFFFFFFF, v, 12);
        float v18 = __shfl_down_sync(0xFFFFFFFF, v, 18);
        float v24 = __shfl_down_sync(0xFFFFFFFF, v, 24);
        a[h] = v + v6 + v12 + v18 + v24;
    }
    if (lane < DH) {
        float* dst = g_m + ((size_t)w * DH + j) * ROW12;
        *(float4*)dst       = make_float4(a[0] * be, a[1] * be, a[2] * be, a[3] * be);
        *(float4*)(dst + 4) = make_float4(a[4] * be, a[5] * be, a[6] * be, a[7] * be);
        dst[8] = a[8] * be;
    }
}

// ---------------- warp-per-node gather + finalize (+ bf16 A emit last layer) --------
__global__ void node_gather_fin_kernel(const float* __restrict__ cbias, int l)
{
    int w = (blockIdx.x * blockDim.x + threadIdx.x) >> 5;
    int lane = threadIdx.x & 31;
    if (w >= NN) return;
    int s = g_noff[w], t = g_noff[w + 1];
    float dv = (t > s) ? (1.0f / (float)(t - s)) : 0.f;
    int j = lane % DH, q = lane / DH;
    bool act = (lane < 30);

    float a[HID];
    #pragma unroll
    for (int h = 0; h < HID; h++) a[h] = 0.f;

    if (act) {
        for (int p = s + q; p < t; p += 5) {
            int2 ke = g_nlist[p];
            float al = g_hsheaf[(size_t)ke.x * DH + j];
            const float* src = g_m + ((size_t)ke.y * DH + j) * ROW12;
            float4 v0 = *(const float4*)src;
            float4 v1 = *(const float4*)(src + 4);
            float  v2 = src[8];
            a[0] += al * v0.x; a[1] += al * v0.y; a[2] += al * v0.z; a[3] += al * v0.w;
            a[4] += al * v1.x; a[5] += al * v1.y; a[6] += al * v1.z; a[7] += al * v1.w;
            a[8] += al * v2;
        }
    }
    #pragma unroll
    for (int h = 0; h < HID; h++) {
        float v = a[h];
        float v6  = __shfl_down_sync(0xFFFFFFFF, v, 6);
        float v12 = __shfl_down_sync(0xFFFFFFFF, v, 12);
        float v18 = __shfl_down_sync(0xFFFFFFFF, v, 18);
        float v24 = __shfl_down_sync(0xFFFFFFFF, v, 24);
        a[h] = v + v6 + v12 + v18 + v24;
    }

    if (lane < DH) {
        size_t idx = (size_t)w * DH + j;
        const float* h0r = g_h0 + idx * ROW12;
        float o[HID];
        #pragma unroll
        for (int h = 0; h < HID; h++)
            o[h] = a[h] * dv + h0r[h] + cbias[l * HID + h];

        if (l == 0) {
            #pragma unroll
            for (int h = 0; h < HID; h++) {
                float v = o[h];
                v = (v > 0.f) ? v : expm1f(v);   // ELU
                g_xproj[idx * HID + h] = v;
            }
        } else {
            __nv_bfloat16* arow = g_Abf + (size_t)w * KTOT + j * HID;
            #pragma unroll
            for (int h = 0; h < HID; h++) {
                float v = o[h];
                __nv_bfloat16 hi = __float2bfloat16(v);
                __nv_bfloat16 lo = __float2bfloat16(v - __bfloat162float(hi));
                arow[h]            = hi;
                arow[KCH + h]      = lo;
                arow[2 * KCH + h]  = hi;
            }
        }
    }
}

// ---------------- B' prep: [B_hi | B_hi | B_lo], B[n][k] = W2[k][n] ----------------
__global__ void prep_B_kernel(const float* __restrict__ W2)
{
    int idx = blockIdx.x * blockDim.x + threadIdx.x;
    if (idx >= B_ROWS_PAD * KTOT) return;
    int n = idx / KTOT, k = idx - n * KTOT;
    int region = k >> 6, j = k & 63;
    __nv_bfloat16 o = __float2bfloat16(0.f);
    if (n < OUTD && j < PROJ) {
        float a = W2[(size_t)j * OUTD + n];
        __nv_bfloat16 h = __float2bfloat16(a);
        if (region == 2) o = __float2bfloat16(a - __bfloat162float(h));
        else             o = h;
    }
    g_Bbf[idx] = o;
}

// ---------------- HMMA lin2 GEMM v2: 128x256 tile, cp.async 2-stage pipeline --------
#define GTM 128
#define GTN 256
#define SA_ST 72                       // smem bf16 stride (conflict-free ldmatrix)
#define SB_ST 72
#define STAGE_A (GTM * SA_ST)          // 9216 bf16
#define STAGE_B (GTN * SB_ST)          // 18432 bf16
#define STAGE_ELEMS (STAGE_A + STAGE_B)            // 27648 bf16 = 55296 B
#define GEMM_SMEM_BYTES (2 * STAGE_ELEMS * 2)      // 110592 B

#define LDSM_X4(r, addr) \
    asm volatile("ldmatrix.sync.aligned.m8n8.x4.shared.b16 {%0,%1,%2,%3}, [%4];" \
        : "=r"((r)[0]), "=r"((r)[1]), "=r"((r)[2]), "=r"((r)[3]) : "r"(addr))
#define MMA16816(d, a, b0, b1) \
    asm volatile("mma.sync.aligned.m16n8k16.row.col.f32.bf16.bf16.f32 " \
        "{%0,%1,%2,%3}, {%4,%5,%6,%7}, {%8,%9}, {%0,%1,%2,%3};" \
        : "+f"((d)[0]), "+f"((d)[1]), "+f"((d)[2]), "+f"((d)[3]) \
        : "r"((a)[0]), "r"((a)[1]), "r"((a)[2]), "r"((a)[3]), "r"(b0), "r"(b1))

__device__ __forceinline__ uint32_t smem_u32(const void* p) {
    uint32_t a;
    asm("{ .reg .u64 t; cvta.to.shared.u64 t, %1; cvt.u32.u64 %0, t; }" : "=r"(a) : "l"(p));
    return a;
}
__device__ __forceinline__ void cp16(uint32_t dst, const void* src) {
    asm volatile("cp.async.cg.shared.global [%0], [%1], 16;" :: "r"(dst), "l"(src));
}

__global__ void __launch_bounds__(512, 1)
lin2_mma_kernel(const float* __restrict__ bias, float* __restrict__ C)
{
    extern __shared__ __nv_bfloat16 smem[];
    __shared__ float sbias[GTN];

    int tid = threadIdx.x, lane = tid & 31, wid = tid >> 5;
    int wm = wid >> 2, wn = wid & 3;            // warp grid 4(M) x 4(N)
    int n0 = blockIdx.x * GTN, m0 = blockIdx.y * GTM;
    uint32_t smb = smem_u32(smem);

    for (int i = tid; i < GTN; i += 512) {
        int n = n0 + i;
        sbias[i] = (n < OUTD) ? bias[n] : 0.f;
    }

    // async load of chunk c into stage st (no guards: operands padded globally)
    auto load_chunk = [&](int c, int st) {
        uint32_t base = smb + (uint32_t)(st * STAGE_ELEMS) * 2;
        #pragma unroll
        for (int i = tid; i < GTM * 8; i += 512) {
            int r = i >> 3, s = i & 7;
            cp16(base + (uint32_t)(r * SA_ST + s * 8) * 2,
                 g_Abf + (size_t)(m0 + r) * KTOT + c * KCH + s * 8);
        }
        uint32_t bbase = base + (uint32_t)STAGE_A * 2;
        #pragma unroll
        for (int i = tid; i < GTN * 8; i += 512) {
            int r = i >> 3, s = i & 7;
            cp16(bbase + (uint32_t)(r * SB_ST + s * 8) * 2,
                 g_Bbf + (size_t)(n0 + r) * KTOT + c * KCH + s * 8);
        }
        asm volatile("cp.async.commit_group;" ::: "memory");
    };

    float acc[2][8][4];
    #pragma unroll
    for (int mt = 0; mt < 2; mt++)
        #pragma unroll
        for (int nt = 0; nt < 8; nt++)
            #pragma unroll
            for (int q = 0; q < 4; q++) acc[mt][nt][q] = 0.f;

    load_chunk(0, 0);

    for (int c = 0; c < NCHUNK; c++) {
        if (c + 1 < NCHUNK) {
            load_chunk(c + 1, (c + 1) & 1);
            asm volatile("cp.async.wait_group 1;" ::: "memory");
        } else {
            asm volatile("cp.async.wait_group 0;" ::: "memory");
        }
        __syncthreads();

        uint32_t a_base = smb + (uint32_t)((c & 1) * STAGE_ELEMS) * 2;
        uint32_t b_base = a_base + (uint32_t)STAGE_A * 2;

        #pragma unroll
        for (int ks = 0; ks < 4; ks++) {
            uint32_t af[2][4], bf[4][4];
            #pragma unroll
            for (int mt = 0; mt < 2; mt++) {
                int row = wm * 32 + mt * 16 + (lane & 15);
                int col = ks * 16 + (lane >> 4) * 8;
                LDSM_X4(af[mt], a_base + (uint32_t)(row * SA_ST + col) * 2);
            }
            #pragma unroll
            for (int p = 0; p < 4; p++) {
                int q = lane >> 3, rl = lane & 7;
                int nrow = wn * 64 + p * 16 + (q >> 1) * 8 + rl;
                int col = ks * 16 + (q & 1) * 8;
                LDSM_X4(bf[p], b_base + (uint32_t)(nrow * SB_ST + col) * 2);
            }
            #pragma unroll
            for (int mt = 0; mt < 2; mt++)
                #pragma unroll
                for (int nt = 0; nt < 8; nt++)
                    MMA16816(acc[mt][nt], af[mt],
                             bf[nt >> 1][(nt & 1) * 2], bf[nt >> 1][(nt & 1) * 2 + 1]);
        }
        __syncthreads();
    }

    // epilogue
    int gid = lane >> 2, tig = lane & 3;
    #pragma unroll
    for (int mt = 0; mt < 2; mt++) {
        int r0 = m0 + wm * 32 + mt * 16 + gid;
        int r1 = r0 + 8;
        #pragma unroll
        for (int nt = 0; nt < 8; nt++) {
            int lc = wn * 64 + nt * 8 + tig * 2;
            int c  = n0 + lc;
            if (c < OUTD) {
                float b0 = sbias[lc], b1 = sbias[lc + 1];
                if (r0 < NN) {
                    float2 v = make_float2(acc[mt][nt][0] + b0, acc[mt][nt][1] + b1);
                    *(float2*)(C + (size_t)r0 * OUTD + c) = v;
                }
                if (r1 < NN) {
                    float2 v = make_float2(acc[mt][nt][2] + b0, acc[mt][nt][3] + b1);
                    *(float2*)(C + (size_t)r1 * OUTD + c) = v;
                }
            }
        }
    }
}

// ---------------- launch ----------------
extern "C" void kernel_launch(void* const* d_in, const int* in_sizes, int n_in,
                              void* d_out, int out_size)
{
    const float* x        = (const float*)d_in[0];
    const float* hedge    = (const float*)d_in[1];
    const int*   node_idx = (const int*)  d_in[2];
    const int*   edge_idx = (const int*)  d_in[3];
    const float* lin_w    = (const float*)d_in[4];
    const float* lin_b    = (const float*)d_in[5];
    const float* s_ln_g   = (const float*)d_in[6];
    const float* s_ln_b   = (const float*)d_in[7];
    const float* sheaf_w  = (const float*)d_in[8];
    const float* sheaf_b  = (const float*)d_in[9];
    const float* c_ln_g   = (const float*)d_in[10];
    const float* c_ln_b   = (const float*)d_in[11];
    const float* conv_w   = (const float*)d_in[12];
    const float* conv_b   = (const float*)d_in[13];
    const float* conv_bias= (const float*)d_in[14];
    const float* lin2_w   = (const float*)d_in[15];
    const float* lin2_b   = (const float*)d_in[16];
    float* out = (float*)d_out;

    // Deterministic, allocation-free attribute set (no static guards).
    cudaFuncSetAttribute(lin2_mma_kernel,
                         cudaFuncAttributeMaxDynamicSharedMemorySize,
                         GEMM_SMEM_BYTES);

    zero_counts_kernel<<<(NN + 255) / 256, 256>>>();
    proj_kernel<<<(NN + EE) / 8, 64>>>(x, hedge, lin_w, lin_b);
    sheaf_kernel<<<(NNZV + 255) / 256, 256>>>(node_idx, edge_idx,
                                              s_ln_g, s_ln_b, sheaf_w, sheaf_b);
    {
        dim3 g1((NN + 1023) / 1024, 2);
        scan1_kernel<<<g1, 1024>>>();
        scan2_kernel<<<1, 64>>>();
        scan3_kernel<<<g1, 1024>>>();
    }
    fill_kernel<<<(NNZV + 255) / 256, 256>>>(node_idx, edge_idx);
    prep_B_kernel<<<(B_ROWS_PAD * KTOT + 255) / 256, 256>>>(lin2_w);

    for (int l = 0; l < NLAY; l++) {
        h0_kernel<<<(NN * DH + 255) / 256, 256>>>(c_ln_g, c_ln_b, conv_w, conv_b, l);
        edge_gather_kernel<<<(EE * 32 + 255) / 256, 256>>>();
        node_gather_fin_kernel<<<(NN * 32 + 255) / 256, 256>>>(conv_bias, l);
    }

    dim3 grid((OUTD + GTN - 1) / GTN, (NN + GTM - 1) / GTM);   // 20 x 157
    lin2_mma_kernel<<<grid, 512, GEMM_SMEM_BYTES>>>(lin2_b, out);
}